// round 9
// baseline (speedup 1.0000x reference)
#include <cuda_runtime.h>
#include <cuda_bf16.h>
#include <cstdint>
#include <math.h>

// Problem constants
#define NB 64
#define NT 512
#define NF 256
#define NP 128
#define NH 256
#define NK 12
#define INV_TEMP 10.0f
#define BT (NB*NT)   // 32768

// ---------------- device scratch (no allocations allowed) ---------------------
__device__ float g_Wf[NF*NP];                       // fused encoder weight 256x128
__device__ float g_bz[NP];                          // fused encoder bias
__device__ float g_z[(size_t)BT*NP];                // z_seq   (b,t,128)
__device__ float g_gi[(size_t)BT*3*NH];             // gi      (b,t,768)
__device__ __align__(16) __nv_bfloat16 g_zp[(size_t)BT*256];       // z split [hi|lo] (for gi)
__device__ __align__(16) __nv_bfloat16 g_cp[(size_t)BT*512];       // c split per-half [hi|lo]
__device__ __align__(16) __nv_bfloat16 g_wps[(size_t)2*1536*256];  // Wp split n-major
__device__ __align__(16) __nv_bfloat16 g_wis[(size_t)768*256];     // Wi split n-major
__device__ __align__(16) int8_t g_predq[(size_t)BT*NK*256];        // pred int8 [a(128)|b(128)]
__device__ float g_preds[(size_t)BT*NK];                           // pred row scales
__device__ __align__(16) int8_t g_zq[(size_t)BT*256];              // z int8 [c(128)|d(128)]
__device__ float g_zs[(size_t)BT];                                 // z row scales

// ---------------- helpers -----------------------------------------------------
__device__ __forceinline__ unsigned smem_u32(const void* p){
    unsigned r;
    asm("{ .reg .u64 t; cvta.to.shared.u64 t, %1; cvt.u32.u64 %0, t; }" : "=r"(r) : "l"(p));
    return r;
}
__device__ __forceinline__ void cp_async16(uint32_t saddr, const void* gptr, uint32_t srcsz){
    asm volatile("cp.async.cg.shared.global [%0], [%1], 16, %2;"
                 :: "r"(saddr), "l"(gptr), "r"(srcsz));
}
#define CP_COMMIT() asm volatile("cp.async.commit_group;" ::: "memory")
#define CP_WAIT0()  asm volatile("cp.async.wait_group 0;" ::: "memory")

__global__ void zero_loss_kernel(float* p){ if (threadIdx.x==0) *p = 0.f; }

__global__ void bz_kernel(const float* __restrict__ b_enc, const float* __restrict__ W_proj,
                          const float* __restrict__ b_proj, float* __restrict__ bz){
    int n = threadIdx.x;            // 128
    float s = b_proj[n];
    for (int e = 0; e < NF; e++) s += b_enc[e] * W_proj[e*NP + n];
    bz[n] = s;
}

// Wp (12,256,128) -> wps[khalf][n=k*128+p][kr(256): hi|lo]
__global__ void repack_wp_kernel(const float* __restrict__ Wp, __nv_bfloat16* __restrict__ wps){
    int idx = blockIdx.x*blockDim.x + threadIdx.x;
    if (idx >= NK*NH*NP) return;
    int p = idx & 127;
    int h = (idx >> 7) & 255;
    int k = idx >> 15;
    float v = Wp[idx];
    __nv_bfloat16 hi = __float2bfloat16(v);
    __nv_bfloat16 lo = __float2bfloat16(v - __bfloat162float(hi));
    int n = k*128 + p;
    int khalf = h >> 7, kr = h & 127;
    size_t base = ((size_t)khalf*1536 + n)*256;
    wps[base + kr]       = hi;
    wps[base + 128 + kr] = lo;
}

// Wi (128,768) -> wis[n][kr(256): hi|lo]
__global__ void repack_wi_kernel(const float* __restrict__ Wi, __nv_bfloat16* __restrict__ wis){
    int idx = blockIdx.x*blockDim.x + threadIdx.x;    // 128*768
    if (idx >= 128*768) return;
    int n = idx % 768;
    int k = idx / 768;
    float v = Wi[idx];
    __nv_bfloat16 hi = __float2bfloat16(v);
    wis[(size_t)n*256 + k]       = hi;
    wis[(size_t)n*256 + 128 + k] = __float2bfloat16(v - __bfloat162float(hi));
}

// z fp32 -> split bf16 [hi(128)|lo(128)]  (gi input)
__global__ void zpack_kernel(const float* __restrict__ z, __nv_bfloat16* __restrict__ zp){
    int idx = blockIdx.x*blockDim.x + threadIdx.x;
    if (idx >= BT*NP) return;
    int row = idx >> 7, c = idx & 127;
    float v = z[idx];
    __nv_bfloat16 h = __float2bfloat16(v);
    zp[(size_t)row*256 + c]       = h;
    zp[(size_t)row*256 + 128 + c] = __float2bfloat16(v - __bfloat162float(h));
}

// z fp32 -> int8 2-chunk [c|d] with per-row scale (loss input)
__global__ void zquant_kernel(const float* __restrict__ z, int8_t* __restrict__ zq,
                              float* __restrict__ zs){
    int row  = blockIdx.x*8 + (threadIdx.x >> 5);
    int lane = threadIdx.x & 31;
    float4 v = reinterpret_cast<const float4*>(z + (size_t)row*128)[lane];
    float m = fmaxf(fmaxf(fabsf(v.x), fabsf(v.y)), fmaxf(fabsf(v.z), fabsf(v.w)));
#pragma unroll
    for (int o = 16; o; o >>= 1) m = fmaxf(m, __shfl_xor_sync(0xFFFFFFFFu, m, o));
    m = fmaxf(m, 1e-30f);
    float s = m * (1.0f/127.0f), inv = 127.0f/m;
    int a0 = __float2int_rn(v.x*inv), a1 = __float2int_rn(v.y*inv);
    int a2 = __float2int_rn(v.z*inv), a3 = __float2int_rn(v.w*inv);
    int d0 = __float2int_rn((v.x*inv - (float)a0)*128.f);
    int d1 = __float2int_rn((v.y*inv - (float)a1)*128.f);
    int d2 = __float2int_rn((v.z*inv - (float)a2)*128.f);
    int d3 = __float2int_rn((v.w*inv - (float)a3)*128.f);
    uint32_t pa = (a0&255) | ((a1&255)<<8) | ((a2&255)<<16) | ((a3&255)<<24);
    uint32_t pd = (d0&255) | ((d1&255)<<8) | ((d2&255)<<16) | ((d3&255)<<24);
    reinterpret_cast<uint32_t*>(zq + (size_t)row*256)[lane]       = pa;
    reinterpret_cast<uint32_t*>(zq + (size_t)row*256 + 128)[lane] = pd;
    if (lane == 0) zs[row] = s;
}

// ---------------- generic tiled GEMM: C = A(MxK) @ B(KxN) + bias --------------
__global__ void __launch_bounds__(256) gemm_bias_kernel(
    const float* __restrict__ A, const float* __restrict__ Bm,
    const float* __restrict__ bias, float* __restrict__ C,
    int M, int N, int K)
{
    __shared__ float As[16][128];
    __shared__ float Bs[16][128];
    const int tid = threadIdx.x;
    const int m0 = blockIdx.y * 128, n0 = blockIdx.x * 128;
    const int tx = tid & 15, ty = tid >> 4;
    float acc[8][8];
#pragma unroll
    for (int i=0;i<8;i++)
#pragma unroll
        for (int j=0;j<8;j++) acc[i][j] = 0.f;

    for (int k0 = 0; k0 < K; k0 += 16) {
#pragma unroll
        for (int it = 0; it < 2; it++) {
            int idx = tid + it*256;
            int r  = idx >> 2;
            int c4 = (idx & 3) << 2;
            const float4 v = *reinterpret_cast<const float4*>(A + (size_t)(m0+r)*K + k0 + c4);
            As[c4+0][r]=v.x; As[c4+1][r]=v.y; As[c4+2][r]=v.z; As[c4+3][r]=v.w;
        }
#pragma unroll
        for (int it = 0; it < 2; it++) {
            int idx = tid + it*256;
            int r  = idx >> 5;
            int c4 = (idx & 31) << 2;
            *reinterpret_cast<float4*>(&Bs[r][c4]) =
                *reinterpret_cast<const float4*>(Bm + (size_t)(k0+r)*N + n0 + c4);
        }
        __syncthreads();
#pragma unroll
        for (int k = 0; k < 16; k++) {
            float a[8], b[8];
            *reinterpret_cast<float4*>(&a[0]) = *reinterpret_cast<float4*>(&As[k][ty*4]);
            *reinterpret_cast<float4*>(&a[4]) = *reinterpret_cast<float4*>(&As[k][ty*4+64]);
            *reinterpret_cast<float4*>(&b[0]) = *reinterpret_cast<float4*>(&Bs[k][tx*4]);
            *reinterpret_cast<float4*>(&b[4]) = *reinterpret_cast<float4*>(&Bs[k][tx*4+64]);
#pragma unroll
            for (int i=0;i<8;i++)
#pragma unroll
                for (int j=0;j<8;j++) acc[i][j] += a[i]*b[j];
        }
        __syncthreads();
    }
#pragma unroll
    for (int i=0;i<8;i++){
        int m = m0 + ty*4 + (i&3) + ((i>>2)<<6);
#pragma unroll
        for (int jg=0;jg<2;jg++){
            int n = n0 + tx*4 + jg*64;
            float4 v;
            v.x = acc[i][jg*4+0]; v.y = acc[i][jg*4+1];
            v.z = acc[i][jg*4+2]; v.w = acc[i][jg*4+3];
            if (bias){
                const float4 bv = *reinterpret_cast<const float4*>(bias + n);
                v.x += bv.x; v.y += bv.y; v.z += bv.z; v.w += bv.w;
            }
            *reinterpret_cast<float4*>(C + (size_t)m*N + n) = v;
        }
    }
}

// ---------------- mma primitives ----------------------------------------------
__device__ __forceinline__ void ldmatrix_x4(uint32_t& r0, uint32_t& r1, uint32_t& r2, uint32_t& r3,
                                            uint32_t addr){
    asm volatile("ldmatrix.sync.aligned.m8n8.x4.shared.b16 {%0,%1,%2,%3}, [%4];"
        : "=r"(r0), "=r"(r1), "=r"(r2), "=r"(r3) : "r"(addr));
}
__device__ __forceinline__ void mma16816(float* d, const uint32_t* a, uint32_t b0, uint32_t b1){
    asm volatile("mma.sync.aligned.m16n8k16.row.col.f32.bf16.bf16.f32 "
        "{%0,%1,%2,%3}, {%4,%5,%6,%7}, {%8,%9}, {%0,%1,%2,%3};"
        : "+f"(d[0]), "+f"(d[1]), "+f"(d[2]), "+f"(d[3])
        : "r"(a[0]), "r"(a[1]), "r"(a[2]), "r"(a[3]), "r"(b0), "r"(b1));
}
__device__ __forceinline__ void mma16832s8(int* d, const uint32_t* a, uint32_t b0, uint32_t b1){
    asm volatile("mma.sync.aligned.m16n8k32.row.col.s32.s8.s8.s32 "
        "{%0,%1,%2,%3}, {%4,%5,%6,%7}, {%8,%9}, {%0,%1,%2,%3};"
        : "+r"(d[0]), "+r"(d[1]), "+r"(d[2]), "+r"(d[3])
        : "r"(a[0]), "r"(a[1]), "r"(a[2]), "r"(a[3]), "r"(b0), "r"(b1));
}

// ---------------- gi GEMM via mma.sync (3-term split bf16) --------------------
#define PRS 264
#define GI_SMEM_BYTES (2*128*PRS*2)

__global__ void __launch_bounds__(256) gi_mma_kernel(
    const __nv_bfloat16* __restrict__ zp, const __nv_bfloat16* __restrict__ wis,
    const float* __restrict__ bi, float* __restrict__ gi)
{
    extern __shared__ __align__(16) char gsm[];
    __nv_bfloat16* SA = reinterpret_cast<__nv_bfloat16*>(gsm);
    __nv_bfloat16* SB = SA + 128*PRS;
    const uint32_t SAb = smem_u32(SA);
    const uint32_t SBb = smem_u32(SB);

    const int tid  = threadIdx.x;
    const int warp = tid >> 5;
    const int lane = tid & 31;
    const int n0   = blockIdx.x * 128;
    const int m0   = blockIdx.y * 128;

    for (int it = 0; it < 16; it++){
        int idx = tid + it*256;
        int r = idx >> 5, u = idx & 31;
        *reinterpret_cast<uint4*>(SA + r*PRS + u*8) =
            *reinterpret_cast<const uint4*>(zp + (size_t)(m0 + r)*256 + u*8);
        *reinterpret_cast<uint4*>(SB + r*PRS + u*8) =
            *reinterpret_cast<const uint4*>(wis + (size_t)(n0 + r)*256 + u*8);
    }
    __syncthreads();

    const uint32_t lrow = (lane & 7) + ((lane >> 3) & 1)*8;
    const uint32_t lcol = (lane >> 4)*8;
    const int mw = warp * 16;

    uint32_t afr[16][4];
#pragma unroll
    for (int kc = 0; kc < 16; kc++){
        uint32_t addr = SAb + ((mw + lrow)*PRS + kc*16 + lcol)*2;
        ldmatrix_x4(afr[kc][0], afr[kc][1], afr[kc][2], afr[kc][3], addr);
    }

    float acc[16][4];
#pragma unroll
    for (int nf = 0; nf < 16; nf++)
#pragma unroll
        for (int i = 0; i < 4; i++) acc[nf][i] = 0.f;

#pragma unroll
    for (int kc = 0; kc < 16; kc++){
#pragma unroll
        for (int nf2 = 0; nf2 < 8; nf2++){
            uint32_t r0,r1,r2,r3;
            uint32_t addr = SBb + ((nf2*16 + lrow)*PRS + kc*16 + lcol)*2;
            ldmatrix_x4(r0, r1, r2, r3, addr);
            if (kc < 8){
                mma16816(acc[nf2*2+0], afr[kc],   r0, r2);
                mma16816(acc[nf2*2+1], afr[kc],   r1, r3);
                mma16816(acc[nf2*2+0], afr[kc+8], r0, r2);
                mma16816(acc[nf2*2+1], afr[kc+8], r1, r3);
            } else {
                mma16816(acc[nf2*2+0], afr[kc-8], r0, r2);
                mma16816(acc[nf2*2+1], afr[kc-8], r1, r3);
            }
        }
    }

    const int r0g = m0 + mw + (lane >> 2);
#pragma unroll
    for (int nf = 0; nf < 16; nf++){
        int c0 = n0 + nf*8 + (lane & 3)*2;
        float b0 = bi[c0], b1 = bi[c0+1];
#pragma unroll
        for (int rr = 0; rr < 2; rr++){
            float2 v;
            v.x = acc[nf][rr*2+0] + b0;
            v.y = acc[nf][rr*2+1] + b1;
            *reinterpret_cast<float2*>(gi + (size_t)(r0g + rr*8)*768 + c0) = v;
        }
    }
}

// ---------------- pred GEMM via mma.sync; epilogue quantizes to int8 ----------
#define PRED_SMEM_BYTES (2*128*PRS*2)

__global__ void __launch_bounds__(256) pred_mma_kernel(
    const __nv_bfloat16* __restrict__ cp, const __nv_bfloat16* __restrict__ wps,
    const float* __restrict__ bp, int8_t* __restrict__ predq, float* __restrict__ preds)
{
    extern __shared__ __align__(16) char psm[];
    __nv_bfloat16* SA = reinterpret_cast<__nv_bfloat16*>(psm);
    __nv_bfloat16* SB = SA + 128*PRS;
    const uint32_t SAb = smem_u32(SA);
    const uint32_t SBb = smem_u32(SB);

    const int tid  = threadIdx.x;
    const int warp = tid >> 5;
    const int lane = tid & 31;
    const int kk   = blockIdx.x;
    const int m0   = blockIdx.y * 128;
    const int n0   = kk * 128;

    const uint32_t lrow = (lane & 7) + ((lane >> 3) & 1)*8;
    const uint32_t lcol = (lane >> 4)*8;
    const int mw = warp * 16;

    float acc[16][4];
#pragma unroll
    for (int nf = 0; nf < 16; nf++)
#pragma unroll
        for (int i = 0; i < 4; i++) acc[nf][i] = 0.f;

    for (int khalf = 0; khalf < 2; khalf++){
        for (int it = 0; it < 16; it++){
            int idx = tid + it*256;
            int r = idx >> 5, u = idx & 31;
            *reinterpret_cast<uint4*>(SA + r*PRS + u*8) =
                *reinterpret_cast<const uint4*>(cp + (size_t)(m0 + r)*512 + khalf*256 + u*8);
            *reinterpret_cast<uint4*>(SB + r*PRS + u*8) =
                *reinterpret_cast<const uint4*>(wps + ((size_t)khalf*1536 + n0 + r)*256 + u*8);
        }
        __syncthreads();

        uint32_t afr[16][4];
#pragma unroll
        for (int kc = 0; kc < 16; kc++){
            uint32_t addr = SAb + ((mw + lrow)*PRS + kc*16 + lcol)*2;
            ldmatrix_x4(afr[kc][0], afr[kc][1], afr[kc][2], afr[kc][3], addr);
        }

#pragma unroll
        for (int kc = 0; kc < 16; kc++){
#pragma unroll
            for (int nf2 = 0; nf2 < 8; nf2++){
                uint32_t r0,r1,r2,r3;
                uint32_t addr = SBb + ((nf2*16 + lrow)*PRS + kc*16 + lcol)*2;
                ldmatrix_x4(r0, r1, r2, r3, addr);
                if (kc < 8){
                    mma16816(acc[nf2*2+0], afr[kc],   r0, r2);
                    mma16816(acc[nf2*2+1], afr[kc],   r1, r3);
                    mma16816(acc[nf2*2+0], afr[kc+8], r0, r2);
                    mma16816(acc[nf2*2+1], afr[kc+8], r1, r3);
                } else {
                    mma16816(acc[nf2*2+0], afr[kc-8], r0, r2);
                    mma16816(acc[nf2*2+1], afr[kc-8], r1, r3);
                }
            }
        }
        __syncthreads();
    }

    // epilogue: bias + INV_TEMP scale, per-row max, 2-chunk int8 quantization
#pragma unroll
    for (int nf = 0; nf < 16; nf++){
        int c0 = nf*8 + (lane & 3)*2;
        float b0 = bp[kk*128 + c0], b1 = bp[kk*128 + c0 + 1];
        acc[nf][0] = (acc[nf][0] + b0) * INV_TEMP;
        acc[nf][1] = (acc[nf][1] + b1) * INV_TEMP;
        acc[nf][2] = (acc[nf][2] + b0) * INV_TEMP;
        acc[nf][3] = (acc[nf][3] + b1) * INV_TEMP;
    }
    float rm0 = 0.f, rm1 = 0.f;
#pragma unroll
    for (int nf = 0; nf < 16; nf++){
        rm0 = fmaxf(rm0, fmaxf(fabsf(acc[nf][0]), fabsf(acc[nf][1])));
        rm1 = fmaxf(rm1, fmaxf(fabsf(acc[nf][2]), fabsf(acc[nf][3])));
    }
#pragma unroll
    for (int o = 1; o <= 2; o <<= 1){
        rm0 = fmaxf(rm0, __shfl_xor_sync(0xFFFFFFFFu, rm0, o));
        rm1 = fmaxf(rm1, __shfl_xor_sync(0xFFFFFFFFu, rm1, o));
    }
    rm0 = fmaxf(rm0, 1e-30f); rm1 = fmaxf(rm1, 1e-30f);
    const float s0 = rm0*(1.f/127.f), inv0 = 127.f/rm0;
    const float s1 = rm1*(1.f/127.f), inv1 = 127.f/rm1;

    const int r0g = m0 + mw + (lane >> 2);
    int8_t* rp0 = predq + ((size_t)r0g*NK + kk)*256;
    int8_t* rp1 = predq + ((size_t)(r0g+8)*NK + kk)*256;
    if ((lane & 3) == 0){
        preds[(size_t)r0g*NK + kk]     = s0;
        preds[(size_t)(r0g+8)*NK + kk] = s1;
    }
#pragma unroll
    for (int nf = 0; nf < 16; nf++){
        int c0 = nf*8 + (lane & 3)*2;
#pragma unroll
        for (int rr = 0; rr < 2; rr++){
            float inv = rr ? inv1 : inv0;
            int8_t* rp = rr ? rp1 : rp0;
            float v0 = acc[nf][rr*2+0], v1 = acc[nf][rr*2+1];
            int a0 = __float2int_rn(v0*inv); a0 = max(min(a0,127),-127);
            int a1 = __float2int_rn(v1*inv); a1 = max(min(a1,127),-127);
            int q0 = __float2int_rn((v0*inv - (float)a0)*128.f); q0 = max(min(q0,127),-127);
            int q1 = __float2int_rn((v1*inv - (float)a1)*128.f); q1 = max(min(q1,127),-127);
            char2 av; av.x = (char)a0; av.y = (char)a1;
            char2 qv; qv.x = (char)q0; qv.y = (char)q1;
            *reinterpret_cast<char2*>(rp + c0)       = av;
            *reinterpret_cast<char2*>(rp + 128 + c0) = qv;
        }
    }
}

// ---------------- GRU scan (writes split-bf16 cp directly) --------------------
__device__ __forceinline__ void st_cluster_f32(unsigned laddr, int rank, float v){
    unsigned raddr;
    asm volatile("mapa.shared::cluster.u32 %0, %1, %2;" : "=r"(raddr) : "r"(laddr), "r"(rank));
    asm volatile("st.shared::cluster.f32 [%0], %1;" :: "r"(raddr), "f"(v) : "memory");
}
__device__ __forceinline__ void cluster_sync_all(){
    asm volatile("barrier.cluster.arrive.aligned;" ::: "memory");
    asm volatile("barrier.cluster.wait.aligned;"   ::: "memory");
}

#define GRU_SMEM_FLOATS 28576
#define GRU_SMEM_BYTES  (GRU_SMEM_FLOATS*4)

__global__ void __launch_bounds__(384) __cluster_dims__(8,1,1)
gru_kernel(const float* __restrict__ gi, const float* __restrict__ Wh,
           const float* __restrict__ bhn, __nv_bfloat16* __restrict__ cp_out)
{
    extern __shared__ float sm[];
    float* Whs   = sm;            // [256][96]
    float* h2    = sm + 24576;    // [2][256][4]
    float* part  = sm + 26624;    // [4][96][4]
    float* ghs   = sm + 28160;    // [4][96]
    float* bhn_s = sm + 28544;    // [32]

    const int tid  = threadIdx.x;
    const int rank = blockIdx.x & 7;
    const int b0   = (blockIdx.x >> 3) * 4;
    const int u0   = rank * 32;

    for (int i = tid; i < 256*96; i += 384){
        int u = i / 96, c = i % 96;
        int gcol = (c >> 5)*256 + u0 + (c & 31);
        Whs[i] = Wh[u*768 + gcol];
    }
    for (int i = tid; i < 2048; i += 384) h2[i] = 0.f;
    if (tid < 32) bhn_s[tid] = bhn[u0 + tid];
    __syncthreads();
    cluster_sync_all();

    const int c  = tid % 96;
    const int q  = tid / 96;
    const int b3 = tid >> 5;
    const int ul = tid & 31;

    int cur = 0;
    for (int t = 0; t < NT; t++){
        float gir=0.f, giz=0.f, gin=0.f;
        if (tid < 128){
            const float* gp = gi + ((size_t)(b0+b3)*NT + t)*768;
            gir = gp[u0+ul]; giz = gp[256+u0+ul]; gin = gp[512+u0+ul];
        }
        {
            const float* hb = h2 + cur*1024;
            float a0=0.f,a1=0.f,a2=0.f,a3=0.f;
            const int ub = q*64;
#pragma unroll 8
            for (int uu = 0; uu < 64; uu++){
                int u = ub + uu;
                float w = Whs[u*96 + c];
                float4 h4 = *reinterpret_cast<const float4*>(hb + u*4);
                a0 += w*h4.x; a1 += w*h4.y; a2 += w*h4.z; a3 += w*h4.w;
            }
            float* pp = part + (q*96 + c)*4;
            pp[0]=a0; pp[1]=a1; pp[2]=a2; pp[3]=a3;
        }
        __syncthreads();
        {
            int c2 = tid % 96, b2 = tid / 96;
            float s = part[(0*96+c2)*4+b2] + part[(1*96+c2)*4+b2]
                    + part[(2*96+c2)*4+b2] + part[(3*96+c2)*4+b2];
            ghs[b2*96 + c2] = s;
        }
        __syncthreads();

        int nxt = cur ^ 1;
        if (tid < 128){
            float hr = ghs[b3*96 + ul];
            float hz = ghs[b3*96 + 32 + ul];
            float hn = ghs[b3*96 + 64 + ul];
            float r  = 1.f/(1.f + expf(-(gir + hr)));
            float zz = 1.f/(1.f + expf(-(giz + hz)));
            float n  = tanhf(gin + r*(hn + bhn_s[ul]));
            float hp = h2[cur*1024 + (u0+ul)*4 + b3];
            float hnew = (1.f - zz)*n + zz*hp;
            int g = u0 + ul;
            size_t base = (((size_t)(b0+b3)*NT + t))*512 + (size_t)(g>>7)*256 + (g & 127);
            __nv_bfloat16 hh = __float2bfloat16(hnew);
            cp_out[base]       = hh;
            cp_out[base + 128] = __float2bfloat16(hnew - __bfloat162float(hh));
            unsigned laddr = smem_u32(h2 + nxt*1024 + (u0+ul)*4 + b3);
#pragma unroll
            for (int r8 = 0; r8 < 8; r8++) st_cluster_f32(laddr, r8, hnew);
        }
        cluster_sync_all();
        cur = nxt;
    }
}

// ---------------- int8 IMMA streaming-softmax contrastive loss ----------------
// logits = sA sZ (a.c + (a.d + b.c)/128); a.c: 4 k32 chunks; cross: 8 chunks [a|b].[d|c].
#define RSI 272
#define LI_TILE (128*RSI)
// SA @0 | SZ0 @LI_TILE | SZ1 @2*LI_TILE | sArr @3*LI_TILE | sZs0 | sZs1 (floats)
#define LOSS_SMEM_BYTES (3*LI_TILE + 3*512)

__global__ void __launch_bounds__(256) loss_mma_kernel(
    const int8_t* __restrict__ predq, const float* __restrict__ preds,
    const int8_t* __restrict__ zq,    const float* __restrict__ zs,
    float* __restrict__ out)
{
    extern __shared__ __align__(16) char lsm[];
    char* SA  = lsm;
    const uint32_t SAb = smem_u32(SA);
    const uint32_t SZb[2] = { SAb + LI_TILE, SAb + 2*LI_TILE };
    float* sArr = reinterpret_cast<float*>(lsm + 3*LI_TILE);
    float* sZs0 = sArr + 128;
    float* sZs1 = sZs0 + 128;
    float* const sZsA[2] = { sZs0, sZs1 };
    __shared__ float wsum[16];

    const int tid  = threadIdx.x;
    const int warp = tid >> 5;
    const int lane = tid & 31;
    const int b    = blockIdx.y;
    const int k    = blockIdx.z + 1;
    const int t0   = blockIdx.x * 128;
    const int Tm   = NT - k;

    // issue Z tile 0 via cp.async
    for (int it = 0; it < 8; it++){
        int idx = tid + it*256;            // 2048 16B units
        int j = idx >> 4, u = idx & 15;
        int jr = k + j;
        uint32_t ok = (jr < NT) ? 16u : 0u;
        int jc = jr < NT ? jr : NT-1;
        cp_async16(SZb[0] + (uint32_t)(j*RSI + u*16),
                   zq + ((size_t)(b*NT) + jc)*256 + u*16, ok);
    }
    CP_COMMIT();
    if (tid < 128){
        int jr = k + tid;
        sZs0[tid] = (jr < NT) ? zs[(size_t)b*NT + jr] : 0.f;
        sArr[tid] = preds[((size_t)(b*NT + t0 + tid))*NK + (k-1)];
    }
    // stage A (int8 rows)
    for (int it = 0; it < 8; it++){
        int idx = tid + it*256;
        int r = idx >> 4, u = idx & 15;
        *reinterpret_cast<uint4*>(SA + r*RSI + u*16) =
            *reinterpret_cast<const uint4*>(
                predq + (((size_t)(b*NT + t0 + r))*NK + (k-1))*256 + u*16);
    }
    __syncthreads();

    const int m0 = warp * 16;
    const uint32_t lrow  = (lane & 7) + ((lane >> 3) & 1)*8;
    const uint32_t lcolB = (lane >> 4)*16;      // byte offset within 32B chunk
    uint32_t afr[8][4];
#pragma unroll
    for (int ch = 0; ch < 8; ch++){
        uint32_t addr = SAb + (uint32_t)((m0 + lrow)*RSI + ch*32) + lcolB;
        ldmatrix_x4(afr[ch][0], afr[ch][1], afr[ch][2], afr[ch][3], addr);
    }

    const int ra = t0 + m0 + (lane >> 2);
    const bool rv0 = ra < Tm, rv1 = (ra + 8) < Tm;
    const float sA0 = sArr[m0 + (lane >> 2)];
    const float sA1 = sArr[m0 + (lane >> 2) + 8];
    float mr[2] = {-1e30f, -1e30f};
    float sr[2] = {0.f, 0.f};
    float tot = 0.f;

    for (int jt = 0; jt < 4; jt++){
        const int j0 = jt * 128;
        CP_WAIT0();
        __syncthreads();
        if (jt < 3){
            const int jn = (jt+1) * 128;
            const uint32_t dst = SZb[(jt+1) & 1];
            for (int it = 0; it < 8; it++){
                int idx = tid + it*256;
                int j = idx >> 4, u = idx & 15;
                int jr = k + jn + j;
                uint32_t ok = (jr < NT) ? 16u : 0u;
                int jc = jr < NT ? jr : NT-1;
                cp_async16(dst + (uint32_t)(j*RSI + u*16),
                           zq + ((size_t)(b*NT) + jc)*256 + u*16, ok);
            }
            CP_COMMIT();
            if (tid < 128){
                int jr = k + jn + tid;
                sZsA[(jt+1)&1][tid] = (jr < NT) ? zs[(size_t)b*NT + jr] : 0.f;
            }
        }
        const uint32_t Zb = SZb[jt & 1];
        const float* sZv = sZsA[jt & 1];

        int acc0[16][4], acc1[16][4];
#pragma unroll
        for (int nf = 0; nf < 16; nf++)
#pragma unroll
            for (int i = 0; i < 4; i++){ acc0[nf][i] = 0; acc1[nf][i] = 0; }

        // main pass: a . c
#pragma unroll
        for (int ch = 0; ch < 4; ch++){
#pragma unroll
            for (int nf2 = 0; nf2 < 8; nf2++){
                uint32_t r0,r1,r2,r3;
                uint32_t addr = Zb + (uint32_t)((nf2*16 + lrow)*RSI + ch*32) + lcolB;
                ldmatrix_x4(r0, r1, r2, r3, addr);
                mma16832s8(acc0[nf2*2+0], afr[ch], r0, r2);
                mma16832s8(acc0[nf2*2+1], afr[ch], r1, r3);
            }
        }
        // cross pass: [a|b] . [d|c]
#pragma unroll
        for (int ch = 0; ch < 8; ch++){
            const uint32_t boff = (ch < 4) ? (128 + ch*32) : ((ch-4)*32);
#pragma unroll
            for (int nf2 = 0; nf2 < 8; nf2++){
                uint32_t r0,r1,r2,r3;
                uint32_t addr = Zb + (uint32_t)((nf2*16 + lrow)*RSI + boff) + lcolB;
                ldmatrix_x4(r0, r1, r2, r3, addr);
                mma16832s8(acc1[nf2*2+0], afr[ch], r0, r2);
                mma16832s8(acc1[nf2*2+1], afr[ch], r1, r3);
            }
        }

        // dequantize into float (reuse acc0 storage as float bits)
#pragma unroll
        for (int nf = 0; nf < 16; nf++){
            int czl = nf*8 + (lane & 3)*2;
            float z0 = sZv[czl], z1 = sZv[czl+1];
            float l0 = sA0 * z0 * fmaf((float)acc1[nf][0], 0.0078125f, (float)acc0[nf][0]);
            float l1 = sA0 * z1 * fmaf((float)acc1[nf][1], 0.0078125f, (float)acc0[nf][1]);
            float l2 = sA1 * z0 * fmaf((float)acc1[nf][2], 0.0078125f, (float)acc0[nf][2]);
            float l3 = sA1 * z1 * fmaf((float)acc1[nf][3], 0.0078125f, (float)acc0[nf][3]);
            acc0[nf][0] = __float_as_int(l0); acc0[nf][1] = __float_as_int(l1);
            acc0[nf][2] = __float_as_int(l2); acc0[nf][3] = __float_as_int(l3);
        }
        const float* lac = reinterpret_cast<const float*>(&acc0[0][0]);

        // ---- streaming softmax over this 128-col tile ----
        if (j0 + 128 <= Tm){
            float tm[2] = {-1e30f, -1e30f};
#pragma unroll
            for (int nf = 0; nf < 16; nf++){
                tm[0] = fmaxf(tm[0], fmaxf(lac[nf*4+0], lac[nf*4+1]));
                tm[1] = fmaxf(tm[1], fmaxf(lac[nf*4+2], lac[nf*4+3]));
            }
#pragma unroll
            for (int o = 1; o <= 2; o <<= 1){
                tm[0] = fmaxf(tm[0], __shfl_xor_sync(0xFFFFFFFFu, tm[0], o));
                tm[1] = fmaxf(tm[1], __shfl_xor_sync(0xFFFFFFFFu, tm[1], o));
            }
#pragma unroll
            for (int rr = 0; rr < 2; rr++){
                float nm = fmaxf(mr[rr], tm[rr]);
                sr[rr] *= __expf(mr[rr] - nm);
                mr[rr] = nm;
            }
            float ls0 = 0.f, ls1 = 0.f, lt0 = 0.f, lt1 = 0.f;
#pragma unroll
            for (int nf = 0; nf < 16; nf++){
                ls0 += __expf(lac[nf*4+0] - mr[0]) + __expf(lac[nf*4+1] - mr[0]);
                ls1 += __expf(lac[nf*4+2] - mr[1]) + __expf(lac[nf*4+3] - mr[1]);
                lt0 += lac[nf*4+0] + lac[nf*4+1];
                lt1 += lac[nf*4+2] + lac[nf*4+3];
            }
            sr[0] += ls0; sr[1] += ls1;
            if (rv0) tot += lt0;
            if (rv1) tot += lt1;
        } else {
            const int cbase = j0 + (lane & 3)*2;
            float tm[2] = {-1e30f, -1e30f};
#pragma unroll
            for (int nf = 0; nf < 16; nf++){
                int c0 = cbase + nf*8;
                bool v0 = c0 < Tm, v1 = (c0+1) < Tm;
                if (v0){ tm[0] = fmaxf(tm[0], lac[nf*4+0]); tm[1] = fmaxf(tm[1], lac[nf*4+2]); }
                if (v1){ tm[0] = fmaxf(tm[0], lac[nf*4+1]); tm[1] = fmaxf(tm[1], lac[nf*4+3]); }
            }
#pragma unroll
            for (int o = 1; o <= 2; o <<= 1){
                tm[0] = fmaxf(tm[0], __shfl_xor_sync(0xFFFFFFFFu, tm[0], o));
                tm[1] = fmaxf(tm[1], __shfl_xor_sync(0xFFFFFFFFu, tm[1], o));
            }
            if (tm[0] > -1e29f){
#pragma unroll
                for (int rr = 0; rr < 2; rr++){
                    float nm = fmaxf(mr[rr], tm[rr]);
                    sr[rr] *= __expf(mr[rr] - nm);
                    mr[rr] = nm;
                }
                float ls0 = 0.f, ls1 = 0.f, lt0 = 0.f, lt1 = 0.f;
#pragma unroll
                for (int nf = 0; nf < 16; nf++){
                    int c0 = cbase + nf*8;
#pragma unroll
                    for (int h = 0; h < 2; h++){
                        if (c0 + h < Tm){
                            ls0 += __expf(lac[nf*4+h]   - mr[0]);
                            ls1 += __expf(lac[nf*4+2+h] - mr[1]);
                            lt0 += lac[nf*4+h]; lt1 += lac[nf*4+2+h];
                        }
                    }
                }
                sr[0] += ls0; sr[1] += ls1;
                if (rv0) tot += lt0;
                if (rv1) tot += lt1;
            }
        }
        __syncthreads();   // all warps done reading Zb before refill
    }

    // ---- finalize ----
#pragma unroll
    for (int o = 1; o <= 2; o <<= 1){
        sr[0] += __shfl_xor_sync(0xFFFFFFFFu, sr[0], o);
        sr[1] += __shfl_xor_sync(0xFFFFFFFFu, sr[1], o);
    }
    float lse = 0.f;
    if ((lane & 3) == 0){
        if (rv0) lse += mr[0] + __logf(sr[0]);
        if (rv1) lse += mr[1] + __logf(sr[1]);
    }
#pragma unroll
    for (int o = 16; o; o >>= 1){
        lse += __shfl_xor_sync(0xFFFFFFFFu, lse, o);
        tot += __shfl_xor_sync(0xFFFFFFFFu, tot, o);
    }
    if (lane == 0){ wsum[warp] = lse; wsum[8+warp] = tot; }
    __syncthreads();
    if (tid == 0){
        float L = 0.f, T = 0.f;
#pragma unroll
        for (int w = 0; w < 8; w++){ L += wsum[w]; T += wsum[8+w]; }
        float inv = 1.0f / ((float)NB * (float)Tm * (float)NK);
        atomicAdd(out, L*inv - T*(inv/(float)Tm));
    }
}

// ---------------- launch ------------------------------------------------------
extern "C" void kernel_launch(void* const* d_in, const int* in_sizes, int n_in,
                              void* d_out, int out_size)
{
    const float* x_seq  = (const float*)d_in[0];
    const float* W_enc  = (const float*)d_in[1];
    const float* b_enc  = (const float*)d_in[2];
    const float* W_proj = (const float*)d_in[3];
    const float* b_proj = (const float*)d_in[4];
    const float* Wi     = (const float*)d_in[5];
    const float* bi     = (const float*)d_in[6];
    const float* Wh     = (const float*)d_in[7];
    const float* bhn    = (const float*)d_in[8];
    const float* Wp     = (const float*)d_in[9];
    const float* bp     = (const float*)d_in[10];
    float* out = (float*)d_out;

    float *Wf, *bz, *zbuf, *gibuf, *predsb, *zsb;
    __nv_bfloat16 *zpb, *cpb, *wpsb, *wisb;
    int8_t *predqb, *zqb;
    cudaGetSymbolAddress((void**)&Wf,     g_Wf);
    cudaGetSymbolAddress((void**)&bz,     g_bz);
    cudaGetSymbolAddress((void**)&zbuf,   g_z);
    cudaGetSymbolAddress((void**)&gibuf,  g_gi);
    cudaGetSymbolAddress((void**)&zpb,    g_zp);
    cudaGetSymbolAddress((void**)&cpb,    g_cp);
    cudaGetSymbolAddress((void**)&wpsb,   g_wps);
    cudaGetSymbolAddress((void**)&wisb,   g_wis);
    cudaGetSymbolAddress((void**)&predqb, g_predq);
    cudaGetSymbolAddress((void**)&predsb, g_preds);
    cudaGetSymbolAddress((void**)&zqb,    g_zq);
    cudaGetSymbolAddress((void**)&zsb,    g_zs);

    cudaFuncSetAttribute(gru_kernel,      cudaFuncAttributeMaxDynamicSharedMemorySize, GRU_SMEM_BYTES);
    cudaFuncSetAttribute(loss_mma_kernel, cudaFuncAttributeMaxDynamicSharedMemorySize, LOSS_SMEM_BYTES);
    cudaFuncSetAttribute(pred_mma_kernel, cudaFuncAttributeMaxDynamicSharedMemorySize, PRED_SMEM_BYTES);
    cudaFuncSetAttribute(gi_mma_kernel,   cudaFuncAttributeMaxDynamicSharedMemorySize, GI_SMEM_BYTES);

    zero_loss_kernel<<<1, 32>>>(out);
    bz_kernel<<<1, 128>>>(b_enc, W_proj, b_proj, bz);

    // Wf = W_enc @ W_proj   (256x128x256)
    gemm_bias_kernel<<<dim3(1,2), 256>>>(W_enc, W_proj, nullptr, Wf, 256, 128, 256);
    // z = x @ Wf + bz       (32768x128x256)
    gemm_bias_kernel<<<dim3(1,256), 256>>>(x_seq, Wf, bz, zbuf, BT, NP, NF);
    // z packs: bf16 split (gi) + int8 2-chunk (loss)
    zpack_kernel<<<(BT*NP+255)/256, 256>>>(zbuf, zpb);
    zquant_kernel<<<BT/8, 256>>>(zbuf, zqb, zsb);
    // Wi split pack
    repack_wi_kernel<<<(128*768+255)/256, 256>>>(Wi, wisb);
    // gi = z @ Wi + bi  (tensor path)
    gi_mma_kernel<<<dim3(6,256), 256, GI_SMEM_BYTES>>>(zpb, wisb, bi, gibuf);
    // Wp split pack
    repack_wp_kernel<<<768, 512>>>(Wp, wpsb);
    // GRU scan (persistent, clustered; writes split c directly)
    gru_kernel<<<128, 384, GRU_SMEM_BYTES>>>(gibuf, Wh, bhn, cpb);
    // pred = (c @ Wp + bp)*INV_TEMP -> int8 2-chunk + row scales
    pred_mma_kernel<<<dim3(12,256), 256, PRED_SMEM_BYTES>>>(cpb, wpsb, bp, predqb, predsb);
    // int8 IMMA streaming-softmax loss
    loss_mma_kernel<<<dim3(4,64,12), 256, LOSS_SMEM_BYTES>>>(predqb, predsb, zqb, zsb, out);
}

// round 11
// speedup vs baseline: 1.2808x; 1.2808x over previous
#include <cuda_runtime.h>
#include <cuda_bf16.h>
#include <cstdint>
#include <math.h>

// Problem constants
#define NB 64
#define NT 512
#define NF 256
#define NP 128
#define NH 256
#define NK 12
#define INV_TEMP 10.0f
#define BT (NB*NT)   // 32768

// ---------------- device scratch (no allocations allowed) ---------------------
__device__ float g_Wf[NF*NP];                       // fused encoder weight 256x128
__device__ float g_bz[NP];                          // fused encoder bias
__device__ float g_gi[(size_t)BT*3*NH];             // gi      (b,t,768)
__device__ __align__(16) __nv_bfloat16 g_zp[(size_t)BT*256];       // z split [hi|lo]
__device__ __align__(16) __nv_bfloat16 g_cp[(size_t)BT*512];       // c split per-half [hi|lo]
__device__ __align__(16) __nv_bfloat16 g_wps[(size_t)2*1536*256];  // Wp split n-major
__device__ __align__(16) __nv_bfloat16 g_wis[(size_t)768*256];     // Wi split n-major

// ---------------- helpers -----------------------------------------------------
__device__ __forceinline__ unsigned smem_u32(const void* p){
    unsigned r;
    asm("{ .reg .u64 t; cvta.to.shared.u64 t, %1; cvt.u32.u64 %0, t; }" : "=r"(r) : "l"(p));
    return r;
}
__device__ __forceinline__ void cp_async16(uint32_t saddr, const void* gptr, uint32_t srcsz){
    asm volatile("cp.async.cg.shared.global [%0], [%1], 16, %2;"
                 :: "r"(saddr), "l"(gptr), "r"(srcsz));
}
#define CP_COMMIT() asm volatile("cp.async.commit_group;" ::: "memory")
#define CP_WAIT0()  asm volatile("cp.async.wait_group 0;" ::: "memory")

__global__ void zero_loss_kernel(float* p){ if (threadIdx.x==0) *p = 0.f; }

__global__ void bz_kernel(const float* __restrict__ b_enc, const float* __restrict__ W_proj,
                          const float* __restrict__ b_proj, float* __restrict__ bz){
    int n = threadIdx.x;            // 128
    float s = b_proj[n];
    for (int e = 0; e < NF; e++) s += b_enc[e] * W_proj[e*NP + n];
    bz[n] = s;
}

// Wp (12,256,128) -> wps[khalf][n=k*128+p][kr(256): hi|lo]
__global__ void repack_wp_kernel(const float* __restrict__ Wp, __nv_bfloat16* __restrict__ wps){
    int idx = blockIdx.x*blockDim.x + threadIdx.x;
    if (idx >= NK*NH*NP) return;
    int p = idx & 127;
    int h = (idx >> 7) & 255;
    int k = idx >> 15;
    float v = Wp[idx];
    __nv_bfloat16 hi = __float2bfloat16(v);
    __nv_bfloat16 lo = __float2bfloat16(v - __bfloat162float(hi));
    int n = k*128 + p;
    int khalf = h >> 7, kr = h & 127;
    size_t base = ((size_t)khalf*1536 + n)*256;
    wps[base + kr]       = hi;
    wps[base + 128 + kr] = lo;
}

// Wi (128,768) -> wis[n][kr(256): hi|lo]
__global__ void repack_wi_kernel(const float* __restrict__ Wi, __nv_bfloat16* __restrict__ wis){
    int idx = blockIdx.x*blockDim.x + threadIdx.x;    // 128*768
    if (idx >= 128*768) return;
    int n = idx % 768;
    int k = idx / 768;
    float v = Wi[idx];
    __nv_bfloat16 hi = __float2bfloat16(v);
    wis[(size_t)n*256 + k]       = hi;
    wis[(size_t)n*256 + 128 + k] = __float2bfloat16(v - __bfloat162float(hi));
}

// ---------------- generic tiled GEMM (used for Wf only) -----------------------
__global__ void __launch_bounds__(256) gemm_bias_kernel(
    const float* __restrict__ A, const float* __restrict__ Bm,
    const float* __restrict__ bias, float* __restrict__ C,
    int M, int N, int K)
{
    __shared__ float As[16][128];
    __shared__ float Bs[16][128];
    const int tid = threadIdx.x;
    const int m0 = blockIdx.y * 128, n0 = blockIdx.x * 128;
    const int tx = tid & 15, ty = tid >> 4;
    float acc[8][8];
#pragma unroll
    for (int i=0;i<8;i++)
#pragma unroll
        for (int j=0;j<8;j++) acc[i][j] = 0.f;

    for (int k0 = 0; k0 < K; k0 += 16) {
#pragma unroll
        for (int it = 0; it < 2; it++) {
            int idx = tid + it*256;
            int r  = idx >> 2;
            int c4 = (idx & 3) << 2;
            const float4 v = *reinterpret_cast<const float4*>(A + (size_t)(m0+r)*K + k0 + c4);
            As[c4+0][r]=v.x; As[c4+1][r]=v.y; As[c4+2][r]=v.z; As[c4+3][r]=v.w;
        }
#pragma unroll
        for (int it = 0; it < 2; it++) {
            int idx = tid + it*256;
            int r  = idx >> 5;
            int c4 = (idx & 31) << 2;
            *reinterpret_cast<float4*>(&Bs[r][c4]) =
                *reinterpret_cast<const float4*>(Bm + (size_t)(k0+r)*N + n0 + c4);
        }
        __syncthreads();
#pragma unroll
        for (int k = 0; k < 16; k++) {
            float a[8], b[8];
            *reinterpret_cast<float4*>(&a[0]) = *reinterpret_cast<float4*>(&As[k][ty*4]);
            *reinterpret_cast<float4*>(&a[4]) = *reinterpret_cast<float4*>(&As[k][ty*4+64]);
            *reinterpret_cast<float4*>(&b[0]) = *reinterpret_cast<float4*>(&Bs[k][tx*4]);
            *reinterpret_cast<float4*>(&b[4]) = *reinterpret_cast<float4*>(&Bs[k][tx*4+64]);
#pragma unroll
            for (int i=0;i<8;i++)
#pragma unroll
                for (int j=0;j<8;j++) acc[i][j] += a[i]*b[j];
        }
        __syncthreads();
    }
#pragma unroll
    for (int i=0;i<8;i++){
        int m = m0 + ty*4 + (i&3) + ((i>>2)<<6);
#pragma unroll
        for (int jg=0;jg<2;jg++){
            int n = n0 + tx*4 + jg*64;
            float4 v;
            v.x = acc[i][jg*4+0]; v.y = acc[i][jg*4+1];
            v.z = acc[i][jg*4+2]; v.w = acc[i][jg*4+3];
            if (bias){
                const float4 bv = *reinterpret_cast<const float4*>(bias + n);
                v.x += bv.x; v.y += bv.y; v.z += bv.z; v.w += bv.w;
            }
            *reinterpret_cast<float4*>(C + (size_t)m*N + n) = v;
        }
    }
}

__device__ __forceinline__ uint32_t pack2bf(__nv_bfloat16 a, __nv_bfloat16 b){
    __nv_bfloat162 t; t.x = a; t.y = b;
    return *reinterpret_cast<uint32_t*>(&t);
}

// ---------------- z GEMM writing split-bf16 zp directly ------------------------
// zp_row = split(x_row @ Wf + bz).  M=BT, N=128, K=256. grid (1, 256).
__global__ void __launch_bounds__(256) zgemm_pack_kernel(
    const float* __restrict__ A, const float* __restrict__ Bm,
    const float* __restrict__ bias, __nv_bfloat16* __restrict__ zp)
{
    __shared__ float As[16][128];
    __shared__ float Bs[16][128];
    const int tid = threadIdx.x;
    const int m0 = blockIdx.y * 128;
    const int tx = tid & 15, ty = tid >> 4;
    float acc[8][8];
#pragma unroll
    for (int i=0;i<8;i++)
#pragma unroll
        for (int j=0;j<8;j++) acc[i][j] = 0.f;

    for (int k0 = 0; k0 < NF; k0 += 16) {
#pragma unroll
        for (int it = 0; it < 2; it++) {
            int idx = tid + it*256;
            int r  = idx >> 2;
            int c4 = (idx & 3) << 2;
            const float4 v = *reinterpret_cast<const float4*>(A + (size_t)(m0+r)*NF + k0 + c4);
            As[c4+0][r]=v.x; As[c4+1][r]=v.y; As[c4+2][r]=v.z; As[c4+3][r]=v.w;
        }
#pragma unroll
        for (int it = 0; it < 2; it++) {
            int idx = tid + it*256;
            int r  = idx >> 5;
            int c4 = (idx & 31) << 2;
            *reinterpret_cast<float4*>(&Bs[r][c4]) =
                *reinterpret_cast<const float4*>(Bm + (size_t)(k0+r)*NP + c4);
        }
        __syncthreads();
#pragma unroll
        for (int k = 0; k < 16; k++) {
            float a[8], b[8];
            *reinterpret_cast<float4*>(&a[0]) = *reinterpret_cast<float4*>(&As[k][ty*4]);
            *reinterpret_cast<float4*>(&a[4]) = *reinterpret_cast<float4*>(&As[k][ty*4+64]);
            *reinterpret_cast<float4*>(&b[0]) = *reinterpret_cast<float4*>(&Bs[k][tx*4]);
            *reinterpret_cast<float4*>(&b[4]) = *reinterpret_cast<float4*>(&Bs[k][tx*4+64]);
#pragma unroll
            for (int i=0;i<8;i++)
#pragma unroll
                for (int j=0;j<8;j++) acc[i][j] += a[i]*b[j];
        }
        __syncthreads();
    }
#pragma unroll
    for (int i=0;i<8;i++){
        int m = m0 + ty*4 + (i&3) + ((i>>2)<<6);
        __nv_bfloat16* rowp = zp + (size_t)m*256;
#pragma unroll
        for (int jg=0;jg<2;jg++){
            int n = tx*4 + jg*64;
            const float4 bv = *reinterpret_cast<const float4*>(bias + n);
            float v0 = acc[i][jg*4+0] + bv.x;
            float v1 = acc[i][jg*4+1] + bv.y;
            float v2 = acc[i][jg*4+2] + bv.z;
            float v3 = acc[i][jg*4+3] + bv.w;
            __nv_bfloat16 h0=__float2bfloat16(v0), h1=__float2bfloat16(v1);
            __nv_bfloat16 h2=__float2bfloat16(v2), h3=__float2bfloat16(v3);
            uint2 hv, lv;
            hv.x = pack2bf(h0,h1); hv.y = pack2bf(h2,h3);
            lv.x = pack2bf(__float2bfloat16(v0-__bfloat162float(h0)),
                           __float2bfloat16(v1-__bfloat162float(h1)));
            lv.y = pack2bf(__float2bfloat16(v2-__bfloat162float(h2)),
                           __float2bfloat16(v3-__bfloat162float(h3)));
            *reinterpret_cast<uint2*>(rowp + n)       = hv;
            *reinterpret_cast<uint2*>(rowp + 128 + n) = lv;
        }
    }
}

// ---------------- mma primitives ----------------------------------------------
__device__ __forceinline__ void ldmatrix_x4(uint32_t& r0, uint32_t& r1, uint32_t& r2, uint32_t& r3,
                                            uint32_t addr){
    asm volatile("ldmatrix.sync.aligned.m8n8.x4.shared.b16 {%0,%1,%2,%3}, [%4];"
        : "=r"(r0), "=r"(r1), "=r"(r2), "=r"(r3) : "r"(addr));
}
__device__ __forceinline__ void mma16816(float* d, const uint32_t* a, uint32_t b0, uint32_t b1){
    asm volatile("mma.sync.aligned.m16n8k16.row.col.f32.bf16.bf16.f32 "
        "{%0,%1,%2,%3}, {%4,%5,%6,%7}, {%8,%9}, {%0,%1,%2,%3};"
        : "+f"(d[0]), "+f"(d[1]), "+f"(d[2]), "+f"(d[3])
        : "r"(a[0]), "r"(a[1]), "r"(a[2]), "r"(a[3]), "r"(b0), "r"(b1));
}

// ---------------- gi GEMM via mma.sync (3-term split bf16) --------------------
#define PRS 264
#define GI_SMEM_BYTES (2*128*PRS*2)

__global__ void __launch_bounds__(256) gi_mma_kernel(
    const __nv_bfloat16* __restrict__ zp, const __nv_bfloat16* __restrict__ wis,
    const float* __restrict__ bi, float* __restrict__ gi)
{
    extern __shared__ __align__(16) char gsm[];
    __nv_bfloat16* SA = reinterpret_cast<__nv_bfloat16*>(gsm);
    __nv_bfloat16* SB = SA + 128*PRS;
    const uint32_t SAb = smem_u32(SA);
    const uint32_t SBb = smem_u32(SB);

    const int tid  = threadIdx.x;
    const int warp = tid >> 5;
    const int lane = tid & 31;
    const int n0   = blockIdx.x * 128;
    const int m0   = blockIdx.y * 128;

    for (int it = 0; it < 16; it++){
        int idx = tid + it*256;
        int r = idx >> 5, u = idx & 31;
        *reinterpret_cast<uint4*>(SA + r*PRS + u*8) =
            *reinterpret_cast<const uint4*>(zp + (size_t)(m0 + r)*256 + u*8);
        *reinterpret_cast<uint4*>(SB + r*PRS + u*8) =
            *reinterpret_cast<const uint4*>(wis + (size_t)(n0 + r)*256 + u*8);
    }
    __syncthreads();

    const uint32_t lrow = (lane & 7) + ((lane >> 3) & 1)*8;
    const uint32_t lcol = (lane >> 4)*8;
    const int mw = warp * 16;

    uint32_t afr[16][4];
#pragma unroll
    for (int kc = 0; kc < 16; kc++){
        uint32_t addr = SAb + ((mw + lrow)*PRS + kc*16 + lcol)*2;
        ldmatrix_x4(afr[kc][0], afr[kc][1], afr[kc][2], afr[kc][3], addr);
    }

    float acc[16][4];
#pragma unroll
    for (int nf = 0; nf < 16; nf++)
#pragma unroll
        for (int i = 0; i < 4; i++) acc[nf][i] = 0.f;

#pragma unroll
    for (int kc = 0; kc < 16; kc++){
#pragma unroll
        for (int nf2 = 0; nf2 < 8; nf2++){
            uint32_t r0,r1,r2,r3;
            uint32_t addr = SBb + ((nf2*16 + lrow)*PRS + kc*16 + lcol)*2;
            ldmatrix_x4(r0, r1, r2, r3, addr);
            if (kc < 8){
                mma16816(acc[nf2*2+0], afr[kc],   r0, r2);
                mma16816(acc[nf2*2+1], afr[kc],   r1, r3);
                mma16816(acc[nf2*2+0], afr[kc+8], r0, r2);
                mma16816(acc[nf2*2+1], afr[kc+8], r1, r3);
            } else {
                mma16816(acc[nf2*2+0], afr[kc-8], r0, r2);
                mma16816(acc[nf2*2+1], afr[kc-8], r1, r3);
            }
        }
    }

    const int r0g = m0 + mw + (lane >> 2);
#pragma unroll
    for (int nf = 0; nf < 16; nf++){
        int c0 = n0 + nf*8 + (lane & 3)*2;
        float b0 = bi[c0], b1 = bi[c0+1];
#pragma unroll
        for (int rr = 0; rr < 2; rr++){
            float2 v;
            v.x = acc[nf][rr*2+0] + b0;
            v.y = acc[nf][rr*2+1] + b1;
            *reinterpret_cast<float2*>(gi + (size_t)(r0g + rr*8)*768 + c0) = v;
        }
    }
}

// ---------------- GRU scan (writes split-bf16 cp directly) --------------------
__device__ __forceinline__ void st_cluster_f32(unsigned laddr, int rank, float v){
    unsigned raddr;
    asm volatile("mapa.shared::cluster.u32 %0, %1, %2;" : "=r"(raddr) : "r"(laddr), "r"(rank));
    asm volatile("st.shared::cluster.f32 [%0], %1;" :: "r"(raddr), "f"(v) : "memory");
}
__device__ __forceinline__ void cluster_sync_all(){
    asm volatile("barrier.cluster.arrive.aligned;" ::: "memory");
    asm volatile("barrier.cluster.wait.aligned;"   ::: "memory");
}

#define GRU_SMEM_FLOATS 28576
#define GRU_SMEM_BYTES  (GRU_SMEM_FLOATS*4)

__global__ void __launch_bounds__(384) __cluster_dims__(8,1,1)
gru_kernel(const float* __restrict__ gi, const float* __restrict__ Wh,
           const float* __restrict__ bhn, __nv_bfloat16* __restrict__ cp_out)
{
    extern __shared__ float sm[];
    float* Whs   = sm;            // [256][96]
    float* h2    = sm + 24576;    // [2][256][4]
    float* part  = sm + 26624;    // [4][96][4]
    float* ghs   = sm + 28160;    // [4][96]
    float* bhn_s = sm + 28544;    // [32]

    const int tid  = threadIdx.x;
    const int rank = blockIdx.x & 7;
    const int b0   = (blockIdx.x >> 3) * 4;
    const int u0   = rank * 32;

    for (int i = tid; i < 256*96; i += 384){
        int u = i / 96, c = i % 96;
        int gcol = (c >> 5)*256 + u0 + (c & 31);
        Whs[i] = Wh[u*768 + gcol];
    }
    for (int i = tid; i < 2048; i += 384) h2[i] = 0.f;
    if (tid < 32) bhn_s[tid] = bhn[u0 + tid];
    __syncthreads();
    cluster_sync_all();

    const int c  = tid % 96;
    const int q  = tid / 96;
    const int b3 = tid >> 5;
    const int ul = tid & 31;

    int cur = 0;
    for (int t = 0; t < NT; t++){
        float gir=0.f, giz=0.f, gin=0.f;
        if (tid < 128){
            const float* gp = gi + ((size_t)(b0+b3)*NT + t)*768;
            gir = gp[u0+ul]; giz = gp[256+u0+ul]; gin = gp[512+u0+ul];
        }
        {
            const float* hb = h2 + cur*1024;
            float a0=0.f,a1=0.f,a2=0.f,a3=0.f;
            const int ub = q*64;
#pragma unroll 8
            for (int uu = 0; uu < 64; uu++){
                int u = ub + uu;
                float w = Whs[u*96 + c];
                float4 h4 = *reinterpret_cast<const float4*>(hb + u*4);
                a0 += w*h4.x; a1 += w*h4.y; a2 += w*h4.z; a3 += w*h4.w;
            }
            float* pp = part + (q*96 + c)*4;
            pp[0]=a0; pp[1]=a1; pp[2]=a2; pp[3]=a3;
        }
        __syncthreads();
        {
            int c2 = tid % 96, b2 = tid / 96;
            float s = part[(0*96+c2)*4+b2] + part[(1*96+c2)*4+b2]
                    + part[(2*96+c2)*4+b2] + part[(3*96+c2)*4+b2];
            ghs[b2*96 + c2] = s;
        }
        __syncthreads();

        int nxt = cur ^ 1;
        if (tid < 128){
            float hr = ghs[b3*96 + ul];
            float hz = ghs[b3*96 + 32 + ul];
            float hn = ghs[b3*96 + 64 + ul];
            float r  = 1.f/(1.f + expf(-(gir + hr)));
            float zz = 1.f/(1.f + expf(-(giz + hz)));
            float n  = tanhf(gin + r*(hn + bhn_s[ul]));
            float hp = h2[cur*1024 + (u0+ul)*4 + b3];
            float hnew = (1.f - zz)*n + zz*hp;
            int g = u0 + ul;
            size_t base = (((size_t)(b0+b3)*NT + t))*512 + (size_t)(g>>7)*256 + (g & 127);
            __nv_bfloat16 hh = __float2bfloat16(hnew);
            cp_out[base]       = hh;
            cp_out[base + 128] = __float2bfloat16(hnew - __bfloat162float(hh));
            unsigned laddr = smem_u32(h2 + nxt*1024 + (u0+ul)*4 + b3);
#pragma unroll
            for (int r8 = 0; r8 < 8; r8++) st_cluster_f32(laddr, r8, hnew);
        }
        cluster_sync_all();
        cur = nxt;
    }
}

// ---------------- fused pred + streaming-softmax loss --------------------------
// Phase 1: A = split_bf16((cp_tile @ Wp[k-1] + bp) * INV_TEMP) computed in-CTA.
// Phase 2: streaming softmax over logits A @ zp^T (identical to R8 loss).
#define LOSS_RS 264
#define LOSS_TILE_BYTES (128*LOSS_RS*2)
#define LOSS_SMEM_BYTES (3*LOSS_TILE_BYTES)

__global__ void __launch_bounds__(256) loss_fused_kernel(
    const __nv_bfloat16* __restrict__ cp, const __nv_bfloat16* __restrict__ wps,
    const float* __restrict__ bp, const __nv_bfloat16* __restrict__ zp,
    float* __restrict__ out)
{
    extern __shared__ __align__(16) char lsm[];
    __nv_bfloat16* SA  = reinterpret_cast<__nv_bfloat16*>(lsm);
    __nv_bfloat16* SZ0 = SA + 128*LOSS_RS;      // doubles as c-tile stage
    __nv_bfloat16* SZ1 = SZ0 + 128*LOSS_RS;     // doubles as Wp-tile stage
    const uint32_t SAb    = smem_u32(SA);
    const uint32_t SZb[2] = { smem_u32(SZ0), smem_u32(SZ1) };
    __shared__ float wsum[16];

    const int tid  = threadIdx.x;
    const int warp = tid >> 5;
    const int lane = tid & 31;
    const int b    = blockIdx.y;
    const int k    = blockIdx.z + 1;
    const int t0   = blockIdx.x * 128;
    const int Tm   = NT - k;
    const int kk   = k - 1;
    const int mg   = b*NT + t0;                 // global row base

    const uint32_t lrow = (lane & 7) + ((lane >> 3) & 1)*8;
    const uint32_t lcol = (lane >> 4)*8;
    const int mw = warp * 16;

    // ================= Phase 1: compute pred A-tile ====================
    float acc[16][4];
#pragma unroll
    for (int nf = 0; nf < 16; nf++)
#pragma unroll
        for (int i = 0; i < 4; i++) acc[nf][i] = 0.f;

    for (int khalf = 0; khalf < 2; khalf++){
        // stage c tile into SZ0, Wp tile into SZ1
        for (int it = 0; it < 16; it++){
            int idx = tid + it*256;
            int r = idx >> 5, u = idx & 31;
            *reinterpret_cast<uint4*>(SZ0 + r*LOSS_RS + u*8) =
                *reinterpret_cast<const uint4*>(cp + (size_t)(mg + r)*512 + khalf*256 + u*8);
            *reinterpret_cast<uint4*>(SZ1 + r*LOSS_RS + u*8) =
                *reinterpret_cast<const uint4*>(wps + ((size_t)khalf*1536 + kk*128 + r)*256 + u*8);
        }
        __syncthreads();

        uint32_t cfr[16][4];
#pragma unroll
        for (int kc = 0; kc < 16; kc++){
            uint32_t addr = SZb[0] + ((mw + lrow)*LOSS_RS + kc*16 + lcol)*2;
            ldmatrix_x4(cfr[kc][0], cfr[kc][1], cfr[kc][2], cfr[kc][3], addr);
        }
#pragma unroll
        for (int kc = 0; kc < 16; kc++){
#pragma unroll
            for (int nf2 = 0; nf2 < 8; nf2++){
                uint32_t r0,r1,r2,r3;
                uint32_t addr = SZb[1] + ((nf2*16 + lrow)*LOSS_RS + kc*16 + lcol)*2;
                ldmatrix_x4(r0, r1, r2, r3, addr);
                if (kc < 8){
                    mma16816(acc[nf2*2+0], cfr[kc],   r0, r2);
                    mma16816(acc[nf2*2+1], cfr[kc],   r1, r3);
                    mma16816(acc[nf2*2+0], cfr[kc+8], r0, r2);
                    mma16816(acc[nf2*2+1], cfr[kc+8], r1, r3);
                } else {
                    mma16816(acc[nf2*2+0], cfr[kc-8], r0, r2);
                    mma16816(acc[nf2*2+1], cfr[kc-8], r1, r3);
                }
            }
        }
        __syncthreads();
    }

    // epilogue: bias + INV_TEMP, split-bf16, store into SA
    {
        const int rloc0 = mw + (lane >> 2);
#pragma unroll
        for (int nf = 0; nf < 16; nf++){
            int c0 = nf*8 + (lane & 3)*2;
            float b0 = bp[kk*128 + c0], b1 = bp[kk*128 + c0 + 1];
#pragma unroll
            for (int rr = 0; rr < 2; rr++){
                float v0 = (acc[nf][rr*2+0] + b0) * INV_TEMP;
                float v1 = (acc[nf][rr*2+1] + b1) * INV_TEMP;
                __nv_bfloat16 h0 = __float2bfloat16(v0);
                __nv_bfloat16 h1 = __float2bfloat16(v1);
                __nv_bfloat16* rp = SA + (rloc0 + rr*8)*LOSS_RS;
                *reinterpret_cast<uint32_t*>(rp + c0) = pack2bf(h0, h1);
                *reinterpret_cast<uint32_t*>(rp + 128 + c0) =
                    pack2bf(__float2bfloat16(v0 - __bfloat162float(h0)),
                            __float2bfloat16(v1 - __bfloat162float(h1)));
            }
        }
    }
    __syncthreads();

    // ================= Phase 2: streaming softmax =====================
    // issue Z tile 0 via cp.async
    for (int it = 0; it < 16; it++){
        int idx = tid + it*256;
        int j = idx >> 5, u = idx & 31;
        int jr = k + j;
        uint32_t ok = (jr < NT) ? 16u : 0u;
        int jc = jr < NT ? jr : NT-1;
        cp_async16(SZb[0] + (uint32_t)(j*LOSS_RS + u*8)*2,
                   zp + ((size_t)(b*NT) + jc)*256 + u*8, ok);
    }
    CP_COMMIT();

    uint32_t afr[16][4];
#pragma unroll
    for (int kc = 0; kc < 16; kc++){
        uint32_t addr = SAb + ((mw + lrow)*LOSS_RS + kc*16 + lcol)*2;
        ldmatrix_x4(afr[kc][0], afr[kc][1], afr[kc][2], afr[kc][3], addr);
    }

    const int ra = t0 + mw + (lane >> 2);
    const bool rv0 = ra < Tm, rv1 = (ra + 8) < Tm;
    float mr[2] = {-1e30f, -1e30f};
    float sr[2] = {0.f, 0.f};
    float tot = 0.f;

    for (int jt = 0; jt < 4; jt++){
        const int j0 = jt * 128;
        CP_WAIT0();
        __syncthreads();
        if (jt < 3){
            const int jn = (jt+1) * 128;
            const uint32_t dst = SZb[(jt+1) & 1];
            for (int it = 0; it < 16; it++){
                int idx = tid + it*256;
                int j = idx >> 5, u = idx & 31;
                int jr = k + jn + j;
                uint32_t ok = (jr < NT) ? 16u : 0u;
                int jc = jr < NT ? jr : NT-1;
                cp_async16(dst + (uint32_t)(j*LOSS_RS + u*8)*2,
                           zp + ((size_t)(b*NT) + jc)*256 + u*8, ok);
            }
            CP_COMMIT();
        }
        const uint32_t Zb = SZb[jt & 1];

        float lac[16][4];
#pragma unroll
        for (int nf = 0; nf < 16; nf++)
#pragma unroll
            for (int i = 0; i < 4; i++) lac[nf][i] = 0.f;

#pragma unroll
        for (int kc = 0; kc < 16; kc++){
#pragma unroll
            for (int nf2 = 0; nf2 < 8; nf2++){
                uint32_t r0,r1,r2,r3;
                uint32_t addr = Zb + (uint32_t)((nf2*16 + lrow)*LOSS_RS + kc*16 + lcol)*2;
                ldmatrix_x4(r0, r1, r2, r3, addr);
                if (kc < 8){
                    mma16816(lac[nf2*2+0], afr[kc],   r0, r2);
                    mma16816(lac[nf2*2+1], afr[kc],   r1, r3);
                    mma16816(lac[nf2*2+0], afr[kc+8], r0, r2);
                    mma16816(lac[nf2*2+1], afr[kc+8], r1, r3);
                } else {
                    mma16816(lac[nf2*2+0], afr[kc-8], r0, r2);
                    mma16816(lac[nf2*2+1], afr[kc-8], r1, r3);
                }
            }
        }

        if (j0 + 128 <= Tm){
            float tm[2] = {-1e30f, -1e30f};
#pragma unroll
            for (int nf = 0; nf < 16; nf++){
                tm[0] = fmaxf(tm[0], fmaxf(lac[nf][0], lac[nf][1]));
                tm[1] = fmaxf(tm[1], fmaxf(lac[nf][2], lac[nf][3]));
            }
#pragma unroll
            for (int o = 1; o <= 2; o <<= 1){
                tm[0] = fmaxf(tm[0], __shfl_xor_sync(0xFFFFFFFFu, tm[0], o));
                tm[1] = fmaxf(tm[1], __shfl_xor_sync(0xFFFFFFFFu, tm[1], o));
            }
#pragma unroll
            for (int rr = 0; rr < 2; rr++){
                float nm = fmaxf(mr[rr], tm[rr]);
                sr[rr] *= __expf(mr[rr] - nm);
                mr[rr] = nm;
            }
            float ls0 = 0.f, ls1 = 0.f, lt0 = 0.f, lt1 = 0.f;
#pragma unroll
            for (int nf = 0; nf < 16; nf++){
                ls0 += __expf(lac[nf][0] - mr[0]) + __expf(lac[nf][1] - mr[0]);
                ls1 += __expf(lac[nf][2] - mr[1]) + __expf(lac[nf][3] - mr[1]);
                lt0 += lac[nf][0] + lac[nf][1];
                lt1 += lac[nf][2] + lac[nf][3];
            }
            sr[0] += ls0; sr[1] += ls1;
            if (rv0) tot += lt0;
            if (rv1) tot += lt1;
        } else {
            const int cbase = j0 + (lane & 3)*2;
            float tm[2] = {-1e30f, -1e30f};
#pragma unroll
            for (int nf = 0; nf < 16; nf++){
                int c0 = cbase + nf*8;
                bool v0 = c0 < Tm, v1 = (c0+1) < Tm;
                if (v0){ tm[0] = fmaxf(tm[0], lac[nf][0]); tm[1] = fmaxf(tm[1], lac[nf][2]); }
                if (v1){ tm[0] = fmaxf(tm[0], lac[nf][1]); tm[1] = fmaxf(tm[1], lac[nf][3]); }
            }
#pragma unroll
            for (int o = 1; o <= 2; o <<= 1){
                tm[0] = fmaxf(tm[0], __shfl_xor_sync(0xFFFFFFFFu, tm[0], o));
                tm[1] = fmaxf(tm[1], __shfl_xor_sync(0xFFFFFFFFu, tm[1], o));
            }
            if (tm[0] > -1e29f){
#pragma unroll
                for (int rr = 0; rr < 2; rr++){
                    float nm = fmaxf(mr[rr], tm[rr]);
                    sr[rr] *= __expf(mr[rr] - nm);
                    mr[rr] = nm;
                }
                float ls0 = 0.f, ls1 = 0.f, lt0 = 0.f, lt1 = 0.f;
#pragma unroll
                for (int nf = 0; nf < 16; nf++){
                    int c0 = cbase + nf*8;
#pragma unroll
                    for (int h = 0; h < 2; h++){
                        if (c0 + h < Tm){
                            ls0 += __expf(lac[nf][h]   - mr[0]);
                            ls1 += __expf(lac[nf][2+h] - mr[1]);
                            lt0 += lac[nf][h]; lt1 += lac[nf][2+h];
                        }
                    }
                }
                sr[0] += ls0; sr[1] += ls1;
                if (rv0) tot += lt0;
                if (rv1) tot += lt1;
            }
        }
        __syncthreads();
    }

    // ---- finalize ----
#pragma unroll
    for (int o = 1; o <= 2; o <<= 1){
        sr[0] += __shfl_xor_sync(0xFFFFFFFFu, sr[0], o);
        sr[1] += __shfl_xor_sync(0xFFFFFFFFu, sr[1], o);
    }
    float lse = 0.f;
    if ((lane & 3) == 0){
        if (rv0) lse += mr[0] + __logf(sr[0]);
        if (rv1) lse += mr[1] + __logf(sr[1]);
    }
#pragma unroll
    for (int o = 16; o; o >>= 1){
        lse += __shfl_xor_sync(0xFFFFFFFFu, lse, o);
        tot += __shfl_xor_sync(0xFFFFFFFFu, tot, o);
    }
    if (lane == 0){ wsum[warp] = lse; wsum[8+warp] = tot; }
    __syncthreads();
    if (tid == 0){
        float L = 0.f, T = 0.f;
#pragma unroll
        for (int w = 0; w < 8; w++){ L += wsum[w]; T += wsum[8+w]; }
        float inv = 1.0f / ((float)NB * (float)Tm * (float)NK);
        atomicAdd(out, L*inv - T*(inv/(float)Tm));
    }
}

// ---------------- launch ------------------------------------------------------
extern "C" void kernel_launch(void* const* d_in, const int* in_sizes, int n_in,
                              void* d_out, int out_size)
{
    const float* x_seq  = (const float*)d_in[0];
    const float* W_enc  = (const float*)d_in[1];
    const float* b_enc  = (const float*)d_in[2];
    const float* W_proj = (const float*)d_in[3];
    const float* b_proj = (const float*)d_in[4];
    const float* Wi     = (const float*)d_in[5];
    const float* bi     = (const float*)d_in[6];
    const float* Wh     = (const float*)d_in[7];
    const float* bhn    = (const float*)d_in[8];
    const float* Wp     = (const float*)d_in[9];
    const float* bp     = (const float*)d_in[10];
    float* out = (float*)d_out;

    float *Wf, *bz, *gibuf;
    __nv_bfloat16 *zpb, *cpb, *wpsb, *wisb;
    cudaGetSymbolAddress((void**)&Wf,    g_Wf);
    cudaGetSymbolAddress((void**)&bz,    g_bz);
    cudaGetSymbolAddress((void**)&gibuf, g_gi);
    cudaGetSymbolAddress((void**)&zpb,   g_zp);
    cudaGetSymbolAddress((void**)&cpb,   g_cp);
    cudaGetSymbolAddress((void**)&wpsb,  g_wps);
    cudaGetSymbolAddress((void**)&wisb,  g_wis);

    cudaFuncSetAttribute(gru_kernel,        cudaFuncAttributeMaxDynamicSharedMemorySize, GRU_SMEM_BYTES);
    cudaFuncSetAttribute(loss_fused_kernel, cudaFuncAttributeMaxDynamicSharedMemorySize, LOSS_SMEM_BYTES);
    cudaFuncSetAttribute(gi_mma_kernel,     cudaFuncAttributeMaxDynamicSharedMemorySize, GI_SMEM_BYTES);

    zero_loss_kernel<<<1, 32>>>(out);
    bz_kernel<<<1, 128>>>(b_enc, W_proj, b_proj, bz);

    // Wf = W_enc @ W_proj   (256x128x256)
    gemm_bias_kernel<<<dim3(1,2), 256>>>(W_enc, W_proj, nullptr, Wf, 256, 128, 256);
    // zp = split(x @ Wf + bz)  — packed epilogue, no fp32 z buffer
    zgemm_pack_kernel<<<dim3(1,256), 256>>>(x_seq, Wf, bz, zpb);
    // Wi split pack
    repack_wi_kernel<<<(128*768+255)/256, 256>>>(Wi, wisb);
    // gi = z @ Wi + bi  (tensor path)
    gi_mma_kernel<<<dim3(6,256), 256, GI_SMEM_BYTES>>>(zpb, wisb, bi, gibuf);
    // Wp split pack
    repack_wp_kernel<<<768, 512>>>(Wp, wpsb);
    // GRU scan (persistent, clustered; writes split c directly)
    gru_kernel<<<128, 384, GRU_SMEM_BYTES>>>(gibuf, Wh, bhn, cpb);
    // fused pred + streaming-softmax loss (no predp buffer)
    loss_fused_kernel<<<dim3(4,64,12), 256, LOSS_SMEM_BYTES>>>(cpb, wpsb, bp, zpb, out);
}

// round 12
// speedup vs baseline: 1.5437x; 1.2053x over previous
#include <cuda_runtime.h>
#include <cuda_bf16.h>
#include <cstdint>
#include <math.h>

// Problem constants
#define NB 64
#define NT 512
#define NF 256
#define NP 128
#define NH 256
#define NK 12
#define INV_TEMP 10.0f
#define BT (NB*NT)   // 32768

// ---------------- device scratch (no allocations allowed) ---------------------
__device__ float g_Wf[NF*NP];                       // fused encoder weight 256x128
__device__ float g_bz[NP];                          // fused encoder bias
__device__ float g_gi[(size_t)BT*3*NH];             // gi      (b,t,768)
__device__ __align__(16) __nv_bfloat16 g_zp[(size_t)BT*256];       // z split [hi|lo]
__device__ __align__(16) __nv_bfloat16 g_cp[(size_t)BT*512];       // c split per-half [hi|lo]
__device__ __align__(16) __nv_bfloat16 g_wps[(size_t)2*1536*256];  // Wp split n-major
__device__ __align__(16) __nv_bfloat16 g_wis[(size_t)768*256];     // Wi split n-major

// ---------------- helpers -----------------------------------------------------
__device__ __forceinline__ unsigned smem_u32(const void* p){
    unsigned r;
    asm("{ .reg .u64 t; cvta.to.shared.u64 t, %1; cvt.u32.u64 %0, t; }" : "=r"(r) : "l"(p));
    return r;
}
__device__ __forceinline__ void cp_async16(uint32_t saddr, const void* gptr, uint32_t srcsz){
    asm volatile("cp.async.cg.shared.global [%0], [%1], 16, %2;"
                 :: "r"(saddr), "l"(gptr), "r"(srcsz));
}
#define CP_COMMIT() asm volatile("cp.async.commit_group;" ::: "memory")
#define CP_WAIT0()  asm volatile("cp.async.wait_group 0;" ::: "memory")

__global__ void zero_loss_kernel(float* p){ if (threadIdx.x==0) *p = 0.f; }

__global__ void bz_kernel(const float* __restrict__ b_enc, const float* __restrict__ W_proj,
                          const float* __restrict__ b_proj, float* __restrict__ bz){
    int n = threadIdx.x;            // 128
    float s = b_proj[n];
    for (int e = 0; e < NF; e++) s += b_enc[e] * W_proj[e*NP + n];
    bz[n] = s;
}

// Wp (12,256,128) -> wps[khalf][n=k*128+p][kr(256): hi|lo]
__global__ void repack_wp_kernel(const float* __restrict__ Wp, __nv_bfloat16* __restrict__ wps){
    int idx = blockIdx.x*blockDim.x + threadIdx.x;
    if (idx >= NK*NH*NP) return;
    int p = idx & 127;
    int h = (idx >> 7) & 255;
    int k = idx >> 15;
    float v = Wp[idx];
    __nv_bfloat16 hi = __float2bfloat16(v);
    __nv_bfloat16 lo = __float2bfloat16(v - __bfloat162float(hi));
    int n = k*128 + p;
    int khalf = h >> 7, kr = h & 127;
    size_t base = ((size_t)khalf*1536 + n)*256;
    wps[base + kr]       = hi;
    wps[base + 128 + kr] = lo;
}

// Wi (128,768) -> wis[n][kr(256): hi|lo]
__global__ void repack_wi_kernel(const float* __restrict__ Wi, __nv_bfloat16* __restrict__ wis){
    int idx = blockIdx.x*blockDim.x + threadIdx.x;    // 128*768
    if (idx >= 128*768) return;
    int n = idx % 768;
    int k = idx / 768;
    float v = Wi[idx];
    __nv_bfloat16 hi = __float2bfloat16(v);
    wis[(size_t)n*256 + k]       = hi;
    wis[(size_t)n*256 + 128 + k] = __float2bfloat16(v - __bfloat162float(hi));
}

// ---------------- generic tiled GEMM (used for Wf only) -----------------------
__global__ void __launch_bounds__(256) gemm_bias_kernel(
    const float* __restrict__ A, const float* __restrict__ Bm,
    const float* __restrict__ bias, float* __restrict__ C,
    int M, int N, int K)
{
    __shared__ float As[16][128];
    __shared__ float Bs[16][128];
    const int tid = threadIdx.x;
    const int m0 = blockIdx.y * 128, n0 = blockIdx.x * 128;
    const int tx = tid & 15, ty = tid >> 4;
    float acc[8][8];
#pragma unroll
    for (int i=0;i<8;i++)
#pragma unroll
        for (int j=0;j<8;j++) acc[i][j] = 0.f;

    for (int k0 = 0; k0 < K; k0 += 16) {
#pragma unroll
        for (int it = 0; it < 2; it++) {
            int idx = tid + it*256;
            int r  = idx >> 2;
            int c4 = (idx & 3) << 2;
            const float4 v = *reinterpret_cast<const float4*>(A + (size_t)(m0+r)*K + k0 + c4);
            As[c4+0][r]=v.x; As[c4+1][r]=v.y; As[c4+2][r]=v.z; As[c4+3][r]=v.w;
        }
#pragma unroll
        for (int it = 0; it < 2; it++) {
            int idx = tid + it*256;
            int r  = idx >> 5;
            int c4 = (idx & 31) << 2;
            *reinterpret_cast<float4*>(&Bs[r][c4]) =
                *reinterpret_cast<const float4*>(Bm + (size_t)(k0+r)*N + n0 + c4);
        }
        __syncthreads();
#pragma unroll
        for (int k = 0; k < 16; k++) {
            float a[8], b[8];
            *reinterpret_cast<float4*>(&a[0]) = *reinterpret_cast<float4*>(&As[k][ty*4]);
            *reinterpret_cast<float4*>(&a[4]) = *reinterpret_cast<float4*>(&As[k][ty*4+64]);
            *reinterpret_cast<float4*>(&b[0]) = *reinterpret_cast<float4*>(&Bs[k][tx*4]);
            *reinterpret_cast<float4*>(&b[4]) = *reinterpret_cast<float4*>(&Bs[k][tx*4+64]);
#pragma unroll
            for (int i=0;i<8;i++)
#pragma unroll
                for (int j=0;j<8;j++) acc[i][j] += a[i]*b[j];
        }
        __syncthreads();
    }
#pragma unroll
    for (int i=0;i<8;i++){
        int m = m0 + ty*4 + (i&3) + ((i>>2)<<6);
#pragma unroll
        for (int jg=0;jg<2;jg++){
            int n = n0 + tx*4 + jg*64;
            float4 v;
            v.x = acc[i][jg*4+0]; v.y = acc[i][jg*4+1];
            v.z = acc[i][jg*4+2]; v.w = acc[i][jg*4+3];
            if (bias){
                const float4 bv = *reinterpret_cast<const float4*>(bias + n);
                v.x += bv.x; v.y += bv.y; v.z += bv.z; v.w += bv.w;
            }
            *reinterpret_cast<float4*>(C + (size_t)m*N + n) = v;
        }
    }
}

__device__ __forceinline__ uint32_t pack2bf(__nv_bfloat16 a, __nv_bfloat16 b){
    __nv_bfloat162 t; t.x = a; t.y = b;
    return *reinterpret_cast<uint32_t*>(&t);
}

// ---------------- z GEMM writing split-bf16 zp directly ------------------------
__global__ void __launch_bounds__(256) zgemm_pack_kernel(
    const float* __restrict__ A, const float* __restrict__ Bm,
    const float* __restrict__ bias, __nv_bfloat16* __restrict__ zp)
{
    __shared__ float As[16][128];
    __shared__ float Bs[16][128];
    const int tid = threadIdx.x;
    const int m0 = blockIdx.y * 128;
    const int tx = tid & 15, ty = tid >> 4;
    float acc[8][8];
#pragma unroll
    for (int i=0;i<8;i++)
#pragma unroll
        for (int j=0;j<8;j++) acc[i][j] = 0.f;

    for (int k0 = 0; k0 < NF; k0 += 16) {
#pragma unroll
        for (int it = 0; it < 2; it++) {
            int idx = tid + it*256;
            int r  = idx >> 2;
            int c4 = (idx & 3) << 2;
            const float4 v = *reinterpret_cast<const float4*>(A + (size_t)(m0+r)*NF + k0 + c4);
            As[c4+0][r]=v.x; As[c4+1][r]=v.y; As[c4+2][r]=v.z; As[c4+3][r]=v.w;
        }
#pragma unroll
        for (int it = 0; it < 2; it++) {
            int idx = tid + it*256;
            int r  = idx >> 5;
            int c4 = (idx & 31) << 2;
            *reinterpret_cast<float4*>(&Bs[r][c4]) =
                *reinterpret_cast<const float4*>(Bm + (size_t)(k0+r)*NP + c4);
        }
        __syncthreads();
#pragma unroll
        for (int k = 0; k < 16; k++) {
            float a[8], b[8];
            *reinterpret_cast<float4*>(&a[0]) = *reinterpret_cast<float4*>(&As[k][ty*4]);
            *reinterpret_cast<float4*>(&a[4]) = *reinterpret_cast<float4*>(&As[k][ty*4+64]);
            *reinterpret_cast<float4*>(&b[0]) = *reinterpret_cast<float4*>(&Bs[k][tx*4]);
            *reinterpret_cast<float4*>(&b[4]) = *reinterpret_cast<float4*>(&Bs[k][tx*4+64]);
#pragma unroll
            for (int i=0;i<8;i++)
#pragma unroll
                for (int j=0;j<8;j++) acc[i][j] += a[i]*b[j];
        }
        __syncthreads();
    }
#pragma unroll
    for (int i=0;i<8;i++){
        int m = m0 + ty*4 + (i&3) + ((i>>2)<<6);
        __nv_bfloat16* rowp = zp + (size_t)m*256;
#pragma unroll
        for (int jg=0;jg<2;jg++){
            int n = tx*4 + jg*64;
            const float4 bv = *reinterpret_cast<const float4*>(bias + n);
            float v0 = acc[i][jg*4+0] + bv.x;
            float v1 = acc[i][jg*4+1] + bv.y;
            float v2 = acc[i][jg*4+2] + bv.z;
            float v3 = acc[i][jg*4+3] + bv.w;
            __nv_bfloat16 h0=__float2bfloat16(v0), h1=__float2bfloat16(v1);
            __nv_bfloat16 h2=__float2bfloat16(v2), h3=__float2bfloat16(v3);
            uint2 hv, lv;
            hv.x = pack2bf(h0,h1); hv.y = pack2bf(h2,h3);
            lv.x = pack2bf(__float2bfloat16(v0-__bfloat162float(h0)),
                           __float2bfloat16(v1-__bfloat162float(h1)));
            lv.y = pack2bf(__float2bfloat16(v2-__bfloat162float(h2)),
                           __float2bfloat16(v3-__bfloat162float(h3)));
            *reinterpret_cast<uint2*>(rowp + n)       = hv;
            *reinterpret_cast<uint2*>(rowp + 128 + n) = lv;
        }
    }
}

// ---------------- mma primitives ----------------------------------------------
__device__ __forceinline__ void ldmatrix_x4(uint32_t& r0, uint32_t& r1, uint32_t& r2, uint32_t& r3,
                                            uint32_t addr){
    asm volatile("ldmatrix.sync.aligned.m8n8.x4.shared.b16 {%0,%1,%2,%3}, [%4];"
        : "=r"(r0), "=r"(r1), "=r"(r2), "=r"(r3) : "r"(addr));
}
__device__ __forceinline__ void mma16816(float* d, const uint32_t* a, uint32_t b0, uint32_t b1){
    asm volatile("mma.sync.aligned.m16n8k16.row.col.f32.bf16.bf16.f32 "
        "{%0,%1,%2,%3}, {%4,%5,%6,%7}, {%8,%9}, {%0,%1,%2,%3};"
        : "+f"(d[0]), "+f"(d[1]), "+f"(d[2]), "+f"(d[3])
        : "r"(a[0]), "r"(a[1]), "r"(a[2]), "r"(a[3]), "r"(b0), "r"(b1));
}

// ---------------- gi GEMM via mma.sync (3-term split bf16) --------------------
#define PRS 264
#define GI_SMEM_BYTES (2*128*PRS*2)

__global__ void __launch_bounds__(256) gi_mma_kernel(
    const __nv_bfloat16* __restrict__ zp, const __nv_bfloat16* __restrict__ wis,
    const float* __restrict__ bi, float* __restrict__ gi)
{
    extern __shared__ __align__(16) char gsm[];
    __nv_bfloat16* SA = reinterpret_cast<__nv_bfloat16*>(gsm);
    __nv_bfloat16* SB = SA + 128*PRS;
    const uint32_t SAb = smem_u32(SA);
    const uint32_t SBb = smem_u32(SB);

    const int tid  = threadIdx.x;
    const int warp = tid >> 5;
    const int lane = tid & 31;
    const int n0   = blockIdx.x * 128;
    const int m0   = blockIdx.y * 128;

    for (int it = 0; it < 16; it++){
        int idx = tid + it*256;
        int r = idx >> 5, u = idx & 31;
        *reinterpret_cast<uint4*>(SA + r*PRS + u*8) =
            *reinterpret_cast<const uint4*>(zp + (size_t)(m0 + r)*256 + u*8);
        *reinterpret_cast<uint4*>(SB + r*PRS + u*8) =
            *reinterpret_cast<const uint4*>(wis + (size_t)(n0 + r)*256 + u*8);
    }
    __syncthreads();

    const uint32_t lrow = (lane & 7) + ((lane >> 3) & 1)*8;
    const uint32_t lcol = (lane >> 4)*8;
    const int mw = warp * 16;

    uint32_t afr[16][4];
#pragma unroll
    for (int kc = 0; kc < 16; kc++){
        uint32_t addr = SAb + ((mw + lrow)*PRS + kc*16 + lcol)*2;
        ldmatrix_x4(afr[kc][0], afr[kc][1], afr[kc][2], afr[kc][3], addr);
    }

    float acc[16][4];
#pragma unroll
    for (int nf = 0; nf < 16; nf++)
#pragma unroll
        for (int i = 0; i < 4; i++) acc[nf][i] = 0.f;

#pragma unroll
    for (int kc = 0; kc < 16; kc++){
#pragma unroll
        for (int nf2 = 0; nf2 < 8; nf2++){
            uint32_t r0,r1,r2,r3;
            uint32_t addr = SBb + ((nf2*16 + lrow)*PRS + kc*16 + lcol)*2;
            ldmatrix_x4(r0, r1, r2, r3, addr);
            if (kc < 8){
                mma16816(acc[nf2*2+0], afr[kc],   r0, r2);
                mma16816(acc[nf2*2+1], afr[kc],   r1, r3);
                mma16816(acc[nf2*2+0], afr[kc+8], r0, r2);
                mma16816(acc[nf2*2+1], afr[kc+8], r1, r3);
            } else {
                mma16816(acc[nf2*2+0], afr[kc-8], r0, r2);
                mma16816(acc[nf2*2+1], afr[kc-8], r1, r3);
            }
        }
    }

    const int r0g = m0 + mw + (lane >> 2);
#pragma unroll
    for (int nf = 0; nf < 16; nf++){
        int c0 = n0 + nf*8 + (lane & 3)*2;
        float b0 = bi[c0], b1 = bi[c0+1];
#pragma unroll
        for (int rr = 0; rr < 2; rr++){
            float2 v;
            v.x = acc[nf][rr*2+0] + b0;
            v.y = acc[nf][rr*2+1] + b1;
            *reinterpret_cast<float2*>(gi + (size_t)(r0g + rr*8)*768 + c0) = v;
        }
    }
}

// ---------------- GRU scan (single intra-step syncthreads) --------------------
__device__ __forceinline__ void st_cluster_f32(unsigned laddr, int rank, float v){
    unsigned raddr;
    asm volatile("mapa.shared::cluster.u32 %0, %1, %2;" : "=r"(raddr) : "r"(laddr), "r"(rank));
    asm volatile("st.shared::cluster.f32 [%0], %1;" :: "r"(raddr), "f"(v) : "memory");
}
__device__ __forceinline__ void cluster_sync_all(){
    asm volatile("barrier.cluster.arrive.aligned;" ::: "memory");
    asm volatile("barrier.cluster.wait.aligned;"   ::: "memory");
}

// smem floats: Whs[256*96] @0 | h2[2][256][4] @24576 | part[16][96] @26624 | bhn_s @28160
#define GRU_SMEM_FLOATS 28192
#define GRU_SMEM_BYTES  (GRU_SMEM_FLOATS*4)

__global__ void __launch_bounds__(384) __cluster_dims__(8,1,1)
gru_kernel(const float* __restrict__ gi, const float* __restrict__ Wh,
           const float* __restrict__ bhn, __nv_bfloat16* __restrict__ cp_out)
{
    extern __shared__ float sm[];
    float* Whs   = sm;            // [256][96]
    float* h2    = sm + 24576;    // [2][256][4]
    float* part  = sm + 26624;    // [q*4+b][96]
    float* bhn_s = sm + 28160;    // [32]

    const int tid  = threadIdx.x;
    const int rank = blockIdx.x & 7;
    const int b0   = (blockIdx.x >> 3) * 4;
    const int u0   = rank * 32;

    for (int i = tid; i < 256*96; i += 384){
        int u = i / 96, c = i % 96;
        int gcol = (c >> 5)*256 + u0 + (c & 31);
        Whs[i] = Wh[u*768 + gcol];
    }
    for (int i = tid; i < 2048; i += 384) h2[i] = 0.f;
    if (tid < 32) bhn_s[tid] = bhn[u0 + tid];
    __syncthreads();
    cluster_sync_all();

    const int c  = tid % 96;
    const int q  = tid / 96;
    const int b3 = tid >> 5;
    const int ul = tid & 31;

    int cur = 0;
    for (int t = 0; t < NT; t++){
        float gir=0.f, giz=0.f, gin=0.f;
        if (tid < 128){
            const float* gp = gi + ((size_t)(b0+b3)*NT + t)*768;
            gir = gp[u0+ul]; giz = gp[256+u0+ul]; gin = gp[512+u0+ul];
        }
        {
            const float* hb = h2 + cur*1024;
            float a0=0.f,a1=0.f,a2=0.f,a3=0.f;
            const int ub = q*64;
#pragma unroll 8
            for (int uu = 0; uu < 64; uu++){
                int u = ub + uu;
                float w = Whs[u*96 + c];
                float4 h4 = *reinterpret_cast<const float4*>(hb + u*4);
                a0 += w*h4.x; a1 += w*h4.y; a2 += w*h4.z; a3 += w*h4.w;
            }
            part[(q*4+0)*96 + c] = a0;
            part[(q*4+1)*96 + c] = a1;
            part[(q*4+2)*96 + c] = a2;
            part[(q*4+3)*96 + c] = a3;
        }
        __syncthreads();

        int nxt = cur ^ 1;
        if (tid < 128){
            float hr = part[(0*4+b3)*96 + ul]      + part[(1*4+b3)*96 + ul]
                     + part[(2*4+b3)*96 + ul]      + part[(3*4+b3)*96 + ul];
            float hz = part[(0*4+b3)*96 + 32 + ul] + part[(1*4+b3)*96 + 32 + ul]
                     + part[(2*4+b3)*96 + 32 + ul] + part[(3*4+b3)*96 + 32 + ul];
            float hn = part[(0*4+b3)*96 + 64 + ul] + part[(1*4+b3)*96 + 64 + ul]
                     + part[(2*4+b3)*96 + 64 + ul] + part[(3*4+b3)*96 + 64 + ul];
            float r  = 1.f/(1.f + expf(-(gir + hr)));
            float zz = 1.f/(1.f + expf(-(giz + hz)));
            float n  = tanhf(gin + r*(hn + bhn_s[ul]));
            float hp = h2[cur*1024 + (u0+ul)*4 + b3];
            float hnew = (1.f - zz)*n + zz*hp;
            int g = u0 + ul;
            size_t base = (((size_t)(b0+b3)*NT + t))*512 + (size_t)(g>>7)*256 + (g & 127);
            __nv_bfloat16 hh = __float2bfloat16(hnew);
            cp_out[base]       = hh;
            cp_out[base + 128] = __float2bfloat16(hnew - __bfloat162float(hh));
            unsigned laddr = smem_u32(h2 + nxt*1024 + (u0+ul)*4 + b3);
#pragma unroll
            for (int r8 = 0; r8 < 8; r8++) st_cluster_f32(laddr, r8, hnew);
        }
        cluster_sync_all();
        cur = nxt;
    }
}

// ---------------- fused pred + streaming-softmax loss --------------------------
// Phase 1: pred A-tile computed in-CTA; A-fragments for phase 2 built IN REGISTERS
// from the phase-1 accumulators (identical fragment layout). No SA buffer.
#define LOSS_RS 264
#define LOSS_TILE_BYTES (128*LOSS_RS*2)
#define LOSS_SMEM_BYTES (2*LOSS_TILE_BYTES)

__global__ void __launch_bounds__(256) loss_fused_kernel(
    const __nv_bfloat16* __restrict__ cp, const __nv_bfloat16* __restrict__ wps,
    const float* __restrict__ bp, const __nv_bfloat16* __restrict__ zp,
    float* __restrict__ out)
{
    extern __shared__ __align__(16) char lsm[];
    __nv_bfloat16* SZ0 = reinterpret_cast<__nv_bfloat16*>(lsm);
    __nv_bfloat16* SZ1 = SZ0 + 128*LOSS_RS;
    const uint32_t SZb[2] = { smem_u32(SZ0), smem_u32(SZ1) };
    __shared__ float wsum[16];

    const int tid  = threadIdx.x;
    const int warp = tid >> 5;
    const int lane = tid & 31;
    const int b    = blockIdx.y;
    const int k    = blockIdx.z + 1;
    const int t0   = blockIdx.x * 128;
    const int Tm   = NT - k;
    const int kk   = k - 1;
    const int mg   = b*NT + t0;

    const uint32_t lrow = (lane & 7) + ((lane >> 3) & 1)*8;
    const uint32_t lcol = (lane >> 4)*8;
    const int mw = warp * 16;

    // ================= Phase 1: pred A-tile ====================
    float acc[16][4];
#pragma unroll
    for (int nf = 0; nf < 16; nf++)
#pragma unroll
        for (int i = 0; i < 4; i++) acc[nf][i] = 0.f;

    for (int khalf = 0; khalf < 2; khalf++){
        for (int it = 0; it < 16; it++){
            int idx = tid + it*256;
            int r = idx >> 5, u = idx & 31;
            *reinterpret_cast<uint4*>(SZ0 + r*LOSS_RS + u*8) =
                *reinterpret_cast<const uint4*>(cp + (size_t)(mg + r)*512 + khalf*256 + u*8);
            *reinterpret_cast<uint4*>(SZ1 + r*LOSS_RS + u*8) =
                *reinterpret_cast<const uint4*>(wps + ((size_t)khalf*1536 + kk*128 + r)*256 + u*8);
        }
        __syncthreads();

        uint32_t cfr[16][4];
#pragma unroll
        for (int kc = 0; kc < 16; kc++){
            uint32_t addr = SZb[0] + ((mw + lrow)*LOSS_RS + kc*16 + lcol)*2;
            ldmatrix_x4(cfr[kc][0], cfr[kc][1], cfr[kc][2], cfr[kc][3], addr);
        }
#pragma unroll
        for (int kc = 0; kc < 16; kc++){
#pragma unroll
            for (int nf2 = 0; nf2 < 8; nf2++){
                uint32_t r0,r1,r2,r3;
                uint32_t addr = SZb[1] + ((nf2*16 + lrow)*LOSS_RS + kc*16 + lcol)*2;
                ldmatrix_x4(r0, r1, r2, r3, addr);
                if (kc < 8){
                    mma16816(acc[nf2*2+0], cfr[kc],   r0, r2);
                    mma16816(acc[nf2*2+1], cfr[kc],   r1, r3);
                    mma16816(acc[nf2*2+0], cfr[kc+8], r0, r2);
                    mma16816(acc[nf2*2+1], cfr[kc+8], r1, r3);
                } else {
                    mma16816(acc[nf2*2+0], cfr[kc-8], r0, r2);
                    mma16816(acc[nf2*2+1], cfr[kc-8], r1, r3);
                }
            }
        }
        __syncthreads();
    }

    // ---- issue Z tile 0 prefetch (buffers now free) ----
    for (int it = 0; it < 16; it++){
        int idx = tid + it*256;
        int j = idx >> 5, u = idx & 31;
        int jr = k + j;
        uint32_t ok = (jr < NT) ? 16u : 0u;
        int jc = jr < NT ? jr : NT-1;
        cp_async16(SZb[0] + (uint32_t)(j*LOSS_RS + u*8)*2,
                   zp + ((size_t)(b*NT) + jc)*256 + u*8, ok);
    }
    CP_COMMIT();

    // ---- build split-bf16 A-fragments in registers (overlaps Z copy) ----
    // frag layout match: afr[kc] regs = {(gr,klo),(gr+8,klo),(gr,khi),(gr+8,khi)}
    //                  = pack(acc[2kc][0..1]), pack(acc[2kc][2..3]),
    //                    pack(acc[2kc+1][0..1]), pack(acc[2kc+1][2..3])
    uint32_t afr[16][4];
    {
        const int ct2 = (lane & 3)*2;
#pragma unroll
        for (int nf = 0; nf < 16; nf++){
            float b0 = bp[kk*128 + nf*8 + ct2];
            float b1 = bp[kk*128 + nf*8 + ct2 + 1];
            acc[nf][0] = (acc[nf][0] + b0) * INV_TEMP;
            acc[nf][1] = (acc[nf][1] + b1) * INV_TEMP;
            acc[nf][2] = (acc[nf][2] + b0) * INV_TEMP;
            acc[nf][3] = (acc[nf][3] + b1) * INV_TEMP;
        }
#pragma unroll
        for (int kc = 0; kc < 8; kc++){
#pragma unroll
            for (int r2 = 0; r2 < 4; r2++){
                int nf = 2*kc + (r2 >> 1);
                int e0 = (r2 & 1)*2, e1 = e0 + 1;
                float v0 = acc[nf][e0], v1 = acc[nf][e1];
                __nv_bfloat16 h0 = __float2bfloat16(v0);
                __nv_bfloat16 h1 = __float2bfloat16(v1);
                afr[kc][r2]   = pack2bf(h0, h1);
                afr[kc+8][r2] = pack2bf(__float2bfloat16(v0 - __bfloat162float(h0)),
                                        __float2bfloat16(v1 - __bfloat162float(h1)));
            }
        }
    }

    // ================= Phase 2: streaming softmax =====================
    const int ra = t0 + mw + (lane >> 2);
    const bool rv0 = ra < Tm, rv1 = (ra + 8) < Tm;
    float mr[2] = {-1e30f, -1e30f};
    float sr[2] = {0.f, 0.f};
    float tot = 0.f;

    for (int jt = 0; jt < 4; jt++){
        const int j0 = jt * 128;
        CP_WAIT0();
        __syncthreads();
        if (jt < 3){
            const int jn = (jt+1) * 128;
            const uint32_t dst = SZb[(jt+1) & 1];
            for (int it = 0; it < 16; it++){
                int idx = tid + it*256;
                int j = idx >> 5, u = idx & 31;
                int jr = k + jn + j;
                uint32_t ok = (jr < NT) ? 16u : 0u;
                int jc = jr < NT ? jr : NT-1;
                cp_async16(dst + (uint32_t)(j*LOSS_RS + u*8)*2,
                           zp + ((size_t)(b*NT) + jc)*256 + u*8, ok);
            }
            CP_COMMIT();
        }
        const uint32_t Zb = SZb[jt & 1];

        float lac[16][4];
#pragma unroll
        for (int nf = 0; nf < 16; nf++)
#pragma unroll
            for (int i = 0; i < 4; i++) lac[nf][i] = 0.f;

#pragma unroll
        for (int kc = 0; kc < 16; kc++){
#pragma unroll
            for (int nf2 = 0; nf2 < 8; nf2++){
                uint32_t r0,r1,r2,r3;
                uint32_t addr = Zb + (uint32_t)((nf2*16 + lrow)*LOSS_RS + kc*16 + lcol)*2;
                ldmatrix_x4(r0, r1, r2, r3, addr);
                if (kc < 8){
                    mma16816(lac[nf2*2+0], afr[kc],   r0, r2);
                    mma16816(lac[nf2*2+1], afr[kc],   r1, r3);
                    mma16816(lac[nf2*2+0], afr[kc+8], r0, r2);
                    mma16816(lac[nf2*2+1], afr[kc+8], r1, r3);
                } else {
                    mma16816(lac[nf2*2+0], afr[kc-8], r0, r2);
                    mma16816(lac[nf2*2+1], afr[kc-8], r1, r3);
                }
            }
        }

        if (j0 + 128 <= Tm){
            float tm[2] = {-1e30f, -1e30f};
#pragma unroll
            for (int nf = 0; nf < 16; nf++){
                tm[0] = fmaxf(tm[0], fmaxf(lac[nf][0], lac[nf][1]));
                tm[1] = fmaxf(tm[1], fmaxf(lac[nf][2], lac[nf][3]));
            }
#pragma unroll
            for (int o = 1; o <= 2; o <<= 1){
                tm[0] = fmaxf(tm[0], __shfl_xor_sync(0xFFFFFFFFu, tm[0], o));
                tm[1] = fmaxf(tm[1], __shfl_xor_sync(0xFFFFFFFFu, tm[1], o));
            }
#pragma unroll
            for (int rr = 0; rr < 2; rr++){
                float nm = fmaxf(mr[rr], tm[rr]);
                sr[rr] *= __expf(mr[rr] - nm);
                mr[rr] = nm;
            }
            float ls0 = 0.f, ls1 = 0.f, lt0 = 0.f, lt1 = 0.f;
#pragma unroll
            for (int nf = 0; nf < 16; nf++){
                ls0 += __expf(lac[nf][0] - mr[0]) + __expf(lac[nf][1] - mr[0]);
                ls1 += __expf(lac[nf][2] - mr[1]) + __expf(lac[nf][3] - mr[1]);
                lt0 += lac[nf][0] + lac[nf][1];
                lt1 += lac[nf][2] + lac[nf][3];
            }
            sr[0] += ls0; sr[1] += ls1;
            if (rv0) tot += lt0;
            if (rv1) tot += lt1;
        } else {
            const int cbase = j0 + (lane & 3)*2;
            float tm[2] = {-1e30f, -1e30f};
#pragma unroll
            for (int nf = 0; nf < 16; nf++){
                int c0 = cbase + nf*8;
                bool v0 = c0 < Tm, v1 = (c0+1) < Tm;
                if (v0){ tm[0] = fmaxf(tm[0], lac[nf][0]); tm[1] = fmaxf(tm[1], lac[nf][2]); }
                if (v1){ tm[0] = fmaxf(tm[0], lac[nf][1]); tm[1] = fmaxf(tm[1], lac[nf][3]); }
            }
#pragma unroll
            for (int o = 1; o <= 2; o <<= 1){
                tm[0] = fmaxf(tm[0], __shfl_xor_sync(0xFFFFFFFFu, tm[0], o));
                tm[1] = fmaxf(tm[1], __shfl_xor_sync(0xFFFFFFFFu, tm[1], o));
            }
            if (tm[0] > -1e29f){
#pragma unroll
                for (int rr = 0; rr < 2; rr++){
                    float nm = fmaxf(mr[rr], tm[rr]);
                    sr[rr] *= __expf(mr[rr] - nm);
                    mr[rr] = nm;
                }
                float ls0 = 0.f, ls1 = 0.f, lt0 = 0.f, lt1 = 0.f;
#pragma unroll
                for (int nf = 0; nf < 16; nf++){
                    int c0 = cbase + nf*8;
#pragma unroll
                    for (int h = 0; h < 2; h++){
                        if (c0 + h < Tm){
                            ls0 += __expf(lac[nf][h]   - mr[0]);
                            ls1 += __expf(lac[nf][2+h] - mr[1]);
                            lt0 += lac[nf][h]; lt1 += lac[nf][2+h];
                        }
                    }
                }
                sr[0] += ls0; sr[1] += ls1;
                if (rv0) tot += lt0;
                if (rv1) tot += lt1;
            }
        }
        __syncthreads();
    }

    // ---- finalize ----
#pragma unroll
    for (int o = 1; o <= 2; o <<= 1){
        sr[0] += __shfl_xor_sync(0xFFFFFFFFu, sr[0], o);
        sr[1] += __shfl_xor_sync(0xFFFFFFFFu, sr[1], o);
    }
    float lse = 0.f;
    if ((lane & 3) == 0){
        if (rv0) lse += mr[0] + __logf(sr[0]);
        if (rv1) lse += mr[1] + __logf(sr[1]);
    }
#pragma unroll
    for (int o = 16; o; o >>= 1){
        lse += __shfl_xor_sync(0xFFFFFFFFu, lse, o);
        tot += __shfl_xor_sync(0xFFFFFFFFu, tot, o);
    }
    if (lane == 0){ wsum[warp] = lse; wsum[8+warp] = tot; }
    __syncthreads();
    if (tid == 0){
        float L = 0.f, T = 0.f;
#pragma unroll
        for (int w = 0; w < 8; w++){ L += wsum[w]; T += wsum[8+w]; }
        float inv = 1.0f / ((float)NB * (float)Tm * (float)NK);
        atomicAdd(out, L*inv - T*(inv/(float)Tm));
    }
}

// ---------------- launch ------------------------------------------------------
extern "C" void kernel_launch(void* const* d_in, const int* in_sizes, int n_in,
                              void* d_out, int out_size)
{
    const float* x_seq  = (const float*)d_in[0];
    const float* W_enc  = (const float*)d_in[1];
    const float* b_enc  = (const float*)d_in[2];
    const float* W_proj = (const float*)d_in[3];
    const float* b_proj = (const float*)d_in[4];
    const float* Wi     = (const float*)d_in[5];
    const float* bi     = (const float*)d_in[6];
    const float* Wh     = (const float*)d_in[7];
    const float* bhn    = (const float*)d_in[8];
    const float* Wp     = (const float*)d_in[9];
    const float* bp     = (const float*)d_in[10];
    float* out = (float*)d_out;

    float *Wf, *bz, *gibuf;
    __nv_bfloat16 *zpb, *cpb, *wpsb, *wisb;
    cudaGetSymbolAddress((void**)&Wf,    g_Wf);
    cudaGetSymbolAddress((void**)&bz,    g_bz);
    cudaGetSymbolAddress((void**)&gibuf, g_gi);
    cudaGetSymbolAddress((void**)&zpb,   g_zp);
    cudaGetSymbolAddress((void**)&cpb,   g_cp);
    cudaGetSymbolAddress((void**)&wpsb,  g_wps);
    cudaGetSymbolAddress((void**)&wisb,  g_wis);

    cudaFuncSetAttribute(gru_kernel,        cudaFuncAttributeMaxDynamicSharedMemorySize, GRU_SMEM_BYTES);
    cudaFuncSetAttribute(loss_fused_kernel, cudaFuncAttributeMaxDynamicSharedMemorySize, LOSS_SMEM_BYTES);
    cudaFuncSetAttribute(gi_mma_kernel,     cudaFuncAttributeMaxDynamicSharedMemorySize, GI_SMEM_BYTES);

    zero_loss_kernel<<<1, 32>>>(out);
    bz_kernel<<<1, 128>>>(b_enc, W_proj, b_proj, bz);

    // Wf = W_enc @ W_proj   (256x128x256)
    gemm_bias_kernel<<<dim3(1,2), 256>>>(W_enc, W_proj, nullptr, Wf, 256, 128, 256);
    // zp = split(x @ Wf + bz)
    zgemm_pack_kernel<<<dim3(1,256), 256>>>(x_seq, Wf, bz, zpb);
    // Wi split pack
    repack_wi_kernel<<<(128*768+255)/256, 256>>>(Wi, wisb);
    // gi = z @ Wi + bi  (tensor path)
    gi_mma_kernel<<<dim3(6,256), 256, GI_SMEM_BYTES>>>(zpb, wisb, bi, gibuf);
    // Wp split pack
    repack_wp_kernel<<<768, 512>>>(Wp, wpsb);
    // GRU scan (persistent, clustered; writes split c directly)
    gru_kernel<<<128, 384, GRU_SMEM_BYTES>>>(gibuf, Wh, bhn, cpb);
    // fused pred + streaming-softmax loss (A-frags in registers, no SA buffer)
    loss_fused_kernel<<<dim3(4,64,12), 256, LOSS_SMEM_BYTES>>>(cpb, wpsb, bp, zpb, out);
}

// round 13
// speedup vs baseline: 1.5747x; 1.0201x over previous
#include <cuda_runtime.h>
#include <cuda_bf16.h>
#include <cstdint>
#include <math.h>

// Problem constants
#define NB 64
#define NT 512
#define NF 256
#define NP 128
#define NH 256
#define NK 12
#define INV_TEMP 10.0f
#define BT (NB*NT)   // 32768

// ---------------- device scratch (no allocations allowed) ---------------------
__device__ float g_Wf[NF*NP];                       // fused encoder weight 256x128
__device__ float g_bz[NP];                          // fused encoder bias
__device__ float g_gi[(size_t)BT*3*NH];             // gi      (b,t,768)
__device__ __align__(16) __nv_bfloat16 g_zp[(size_t)BT*256];       // z split [hi|lo]
__device__ __align__(16) __nv_bfloat16 g_cp[(size_t)BT*512];       // c split per-half [hi|lo]
__device__ __align__(16) __nv_bfloat16 g_wps[(size_t)2*1536*256];  // Wp split n-major
__device__ __align__(16) __nv_bfloat16 g_wis[(size_t)768*256];     // Wi split n-major

// ---------------- helpers -----------------------------------------------------
__device__ __forceinline__ unsigned smem_u32(const void* p){
    unsigned r;
    asm("{ .reg .u64 t; cvta.to.shared.u64 t, %1; cvt.u32.u64 %0, t; }" : "=r"(r) : "l"(p));
    return r;
}
__device__ __forceinline__ void cp_async16(uint32_t saddr, const void* gptr, uint32_t srcsz){
    asm volatile("cp.async.cg.shared.global [%0], [%1], 16, %2;"
                 :: "r"(saddr), "l"(gptr), "r"(srcsz));
}
#define CP_COMMIT() asm volatile("cp.async.commit_group;" ::: "memory")
#define CP_WAIT0()  asm volatile("cp.async.wait_group 0;" ::: "memory")

__global__ void zero_loss_kernel(float* p){ if (threadIdx.x==0) *p = 0.f; }

__global__ void bz_kernel(const float* __restrict__ b_enc, const float* __restrict__ W_proj,
                          const float* __restrict__ b_proj, float* __restrict__ bz){
    int n = threadIdx.x;            // 128
    float s = b_proj[n];
    for (int e = 0; e < NF; e++) s += b_enc[e] * W_proj[e*NP + n];
    bz[n] = s;
}

// Wp (12,256,128) -> wps[khalf][n=k*128+p][kr(256): hi|lo]
__global__ void repack_wp_kernel(const float* __restrict__ Wp, __nv_bfloat16* __restrict__ wps){
    int idx = blockIdx.x*blockDim.x + threadIdx.x;
    if (idx >= NK*NH*NP) return;
    int p = idx & 127;
    int h = (idx >> 7) & 255;
    int k = idx >> 15;
    float v = Wp[idx];
    __nv_bfloat16 hi = __float2bfloat16(v);
    __nv_bfloat16 lo = __float2bfloat16(v - __bfloat162float(hi));
    int n = k*128 + p;
    int khalf = h >> 7, kr = h & 127;
    size_t base = ((size_t)khalf*1536 + n)*256;
    wps[base + kr]       = hi;
    wps[base + 128 + kr] = lo;
}

// Wi (128,768) -> wis[n][kr(256): hi|lo]
__global__ void repack_wi_kernel(const float* __restrict__ Wi, __nv_bfloat16* __restrict__ wis){
    int idx = blockIdx.x*blockDim.x + threadIdx.x;    // 128*768
    if (idx >= 128*768) return;
    int n = idx % 768;
    int k = idx / 768;
    float v = Wi[idx];
    __nv_bfloat16 hi = __float2bfloat16(v);
    wis[(size_t)n*256 + k]       = hi;
    wis[(size_t)n*256 + 128 + k] = __float2bfloat16(v - __bfloat162float(hi));
}

// ---------------- generic tiled GEMM (used for Wf only) -----------------------
__global__ void __launch_bounds__(256) gemm_bias_kernel(
    const float* __restrict__ A, const float* __restrict__ Bm,
    const float* __restrict__ bias, float* __restrict__ C,
    int M, int N, int K)
{
    __shared__ float As[16][128];
    __shared__ float Bs[16][128];
    const int tid = threadIdx.x;
    const int m0 = blockIdx.y * 128, n0 = blockIdx.x * 128;
    const int tx = tid & 15, ty = tid >> 4;
    float acc[8][8];
#pragma unroll
    for (int i=0;i<8;i++)
#pragma unroll
        for (int j=0;j<8;j++) acc[i][j] = 0.f;

    for (int k0 = 0; k0 < K; k0 += 16) {
#pragma unroll
        for (int it = 0; it < 2; it++) {
            int idx = tid + it*256;
            int r  = idx >> 2;
            int c4 = (idx & 3) << 2;
            const float4 v = *reinterpret_cast<const float4*>(A + (size_t)(m0+r)*K + k0 + c4);
            As[c4+0][r]=v.x; As[c4+1][r]=v.y; As[c4+2][r]=v.z; As[c4+3][r]=v.w;
        }
#pragma unroll
        for (int it = 0; it < 2; it++) {
            int idx = tid + it*256;
            int r  = idx >> 5;
            int c4 = (idx & 31) << 2;
            *reinterpret_cast<float4*>(&Bs[r][c4]) =
                *reinterpret_cast<const float4*>(Bm + (size_t)(k0+r)*N + n0 + c4);
        }
        __syncthreads();
#pragma unroll
        for (int k = 0; k < 16; k++) {
            float a[8], b[8];
            *reinterpret_cast<float4*>(&a[0]) = *reinterpret_cast<float4*>(&As[k][ty*4]);
            *reinterpret_cast<float4*>(&a[4]) = *reinterpret_cast<float4*>(&As[k][ty*4+64]);
            *reinterpret_cast<float4*>(&b[0]) = *reinterpret_cast<float4*>(&Bs[k][tx*4]);
            *reinterpret_cast<float4*>(&b[4]) = *reinterpret_cast<float4*>(&Bs[k][tx*4+64]);
#pragma unroll
            for (int i=0;i<8;i++)
#pragma unroll
                for (int j=0;j<8;j++) acc[i][j] += a[i]*b[j];
        }
        __syncthreads();
    }
#pragma unroll
    for (int i=0;i<8;i++){
        int m = m0 + ty*4 + (i&3) + ((i>>2)<<6);
#pragma unroll
        for (int jg=0;jg<2;jg++){
            int n = n0 + tx*4 + jg*64;
            float4 v;
            v.x = acc[i][jg*4+0]; v.y = acc[i][jg*4+1];
            v.z = acc[i][jg*4+2]; v.w = acc[i][jg*4+3];
            if (bias){
                const float4 bv = *reinterpret_cast<const float4*>(bias + n);
                v.x += bv.x; v.y += bv.y; v.z += bv.z; v.w += bv.w;
            }
            *reinterpret_cast<float4*>(C + (size_t)m*N + n) = v;
        }
    }
}

__device__ __forceinline__ uint32_t pack2bf(__nv_bfloat16 a, __nv_bfloat16 b){
    __nv_bfloat162 t; t.x = a; t.y = b;
    return *reinterpret_cast<uint32_t*>(&t);
}

// ---------------- z GEMM writing split-bf16 zp directly ------------------------
__global__ void __launch_bounds__(256) zgemm_pack_kernel(
    const float* __restrict__ A, const float* __restrict__ Bm,
    const float* __restrict__ bias, __nv_bfloat16* __restrict__ zp)
{
    __shared__ float As[16][128];
    __shared__ float Bs[16][128];
    const int tid = threadIdx.x;
    const int m0 = blockIdx.y * 128;
    const int tx = tid & 15, ty = tid >> 4;
    float acc[8][8];
#pragma unroll
    for (int i=0;i<8;i++)
#pragma unroll
        for (int j=0;j<8;j++) acc[i][j] = 0.f;

    for (int k0 = 0; k0 < NF; k0 += 16) {
#pragma unroll
        for (int it = 0; it < 2; it++) {
            int idx = tid + it*256;
            int r  = idx >> 2;
            int c4 = (idx & 3) << 2;
            const float4 v = *reinterpret_cast<const float4*>(A + (size_t)(m0+r)*NF + k0 + c4);
            As[c4+0][r]=v.x; As[c4+1][r]=v.y; As[c4+2][r]=v.z; As[c4+3][r]=v.w;
        }
#pragma unroll
        for (int it = 0; it < 2; it++) {
            int idx = tid + it*256;
            int r  = idx >> 5;
            int c4 = (idx & 31) << 2;
            *reinterpret_cast<float4*>(&Bs[r][c4]) =
                *reinterpret_cast<const float4*>(Bm + (size_t)(k0+r)*NP + c4);
        }
        __syncthreads();
#pragma unroll
        for (int k = 0; k < 16; k++) {
            float a[8], b[8];
            *reinterpret_cast<float4*>(&a[0]) = *reinterpret_cast<float4*>(&As[k][ty*4]);
            *reinterpret_cast<float4*>(&a[4]) = *reinterpret_cast<float4*>(&As[k][ty*4+64]);
            *reinterpret_cast<float4*>(&b[0]) = *reinterpret_cast<float4*>(&Bs[k][tx*4]);
            *reinterpret_cast<float4*>(&b[4]) = *reinterpret_cast<float4*>(&Bs[k][tx*4+64]);
#pragma unroll
            for (int i=0;i<8;i++)
#pragma unroll
                for (int j=0;j<8;j++) acc[i][j] += a[i]*b[j];
        }
        __syncthreads();
    }
#pragma unroll
    for (int i=0;i<8;i++){
        int m = m0 + ty*4 + (i&3) + ((i>>2)<<6);
        __nv_bfloat16* rowp = zp + (size_t)m*256;
#pragma unroll
        for (int jg=0;jg<2;jg++){
            int n = tx*4 + jg*64;
            const float4 bv = *reinterpret_cast<const float4*>(bias + n);
            float v0 = acc[i][jg*4+0] + bv.x;
            float v1 = acc[i][jg*4+1] + bv.y;
            float v2 = acc[i][jg*4+2] + bv.z;
            float v3 = acc[i][jg*4+3] + bv.w;
            __nv_bfloat16 h0=__float2bfloat16(v0), h1=__float2bfloat16(v1);
            __nv_bfloat16 h2=__float2bfloat16(v2), h3=__float2bfloat16(v3);
            uint2 hv, lv;
            hv.x = pack2bf(h0,h1); hv.y = pack2bf(h2,h3);
            lv.x = pack2bf(__float2bfloat16(v0-__bfloat162float(h0)),
                           __float2bfloat16(v1-__bfloat162float(h1)));
            lv.y = pack2bf(__float2bfloat16(v2-__bfloat162float(h2)),
                           __float2bfloat16(v3-__bfloat162float(h3)));
            *reinterpret_cast<uint2*>(rowp + n)       = hv;
            *reinterpret_cast<uint2*>(rowp + 128 + n) = lv;
        }
    }
}

// ---------------- mma primitives ----------------------------------------------
__device__ __forceinline__ void ldmatrix_x4(uint32_t& r0, uint32_t& r1, uint32_t& r2, uint32_t& r3,
                                            uint32_t addr){
    asm volatile("ldmatrix.sync.aligned.m8n8.x4.shared.b16 {%0,%1,%2,%3}, [%4];"
        : "=r"(r0), "=r"(r1), "=r"(r2), "=r"(r3) : "r"(addr));
}
__device__ __forceinline__ void mma16816(float* d, const uint32_t* a, uint32_t b0, uint32_t b1){
    asm volatile("mma.sync.aligned.m16n8k16.row.col.f32.bf16.bf16.f32 "
        "{%0,%1,%2,%3}, {%4,%5,%6,%7}, {%8,%9}, {%0,%1,%2,%3};"
        : "+f"(d[0]), "+f"(d[1]), "+f"(d[2]), "+f"(d[3])
        : "r"(a[0]), "r"(a[1]), "r"(a[2]), "r"(a[3]), "r"(b0), "r"(b1));
}

// ---------------- gi GEMM via mma.sync (3-term split bf16) --------------------
#define PRS 264
#define GI_SMEM_BYTES (2*128*PRS*2)

__global__ void __launch_bounds__(256) gi_mma_kernel(
    const __nv_bfloat16* __restrict__ zp, const __nv_bfloat16* __restrict__ wis,
    const float* __restrict__ bi, float* __restrict__ gi)
{
    extern __shared__ __align__(16) char gsm[];
    __nv_bfloat16* SA = reinterpret_cast<__nv_bfloat16*>(gsm);
    __nv_bfloat16* SB = SA + 128*PRS;
    const uint32_t SAb = smem_u32(SA);
    const uint32_t SBb = smem_u32(SB);

    const int tid  = threadIdx.x;
    const int warp = tid >> 5;
    const int lane = tid & 31;
    const int n0   = blockIdx.x * 128;
    const int m0   = blockIdx.y * 128;

    for (int it = 0; it < 16; it++){
        int idx = tid + it*256;
        int r = idx >> 5, u = idx & 31;
        *reinterpret_cast<uint4*>(SA + r*PRS + u*8) =
            *reinterpret_cast<const uint4*>(zp + (size_t)(m0 + r)*256 + u*8);
        *reinterpret_cast<uint4*>(SB + r*PRS + u*8) =
            *reinterpret_cast<const uint4*>(wis + (size_t)(n0 + r)*256 + u*8);
    }
    __syncthreads();

    const uint32_t lrow = (lane & 7) + ((lane >> 3) & 1)*8;
    const uint32_t lcol = (lane >> 4)*8;
    const int mw = warp * 16;

    uint32_t afr[16][4];
#pragma unroll
    for (int kc = 0; kc < 16; kc++){
        uint32_t addr = SAb + ((mw + lrow)*PRS + kc*16 + lcol)*2;
        ldmatrix_x4(afr[kc][0], afr[kc][1], afr[kc][2], afr[kc][3], addr);
    }

    float acc[16][4];
#pragma unroll
    for (int nf = 0; nf < 16; nf++)
#pragma unroll
        for (int i = 0; i < 4; i++) acc[nf][i] = 0.f;

#pragma unroll
    for (int kc = 0; kc < 16; kc++){
#pragma unroll
        for (int nf2 = 0; nf2 < 8; nf2++){
            uint32_t r0,r1,r2,r3;
            uint32_t addr = SBb + ((nf2*16 + lrow)*PRS + kc*16 + lcol)*2;
            ldmatrix_x4(r0, r1, r2, r3, addr);
            if (kc < 8){
                mma16816(acc[nf2*2+0], afr[kc],   r0, r2);
                mma16816(acc[nf2*2+1], afr[kc],   r1, r3);
                mma16816(acc[nf2*2+0], afr[kc+8], r0, r2);
                mma16816(acc[nf2*2+1], afr[kc+8], r1, r3);
            } else {
                mma16816(acc[nf2*2+0], afr[kc-8], r0, r2);
                mma16816(acc[nf2*2+1], afr[kc-8], r1, r3);
            }
        }
    }

    const int r0g = m0 + mw + (lane >> 2);
#pragma unroll
    for (int nf = 0; nf < 16; nf++){
        int c0 = n0 + nf*8 + (lane & 3)*2;
        float b0 = bi[c0], b1 = bi[c0+1];
#pragma unroll
        for (int rr = 0; rr < 2; rr++){
            float2 v;
            v.x = acc[nf][rr*2+0] + b0;
            v.y = acc[nf][rr*2+1] + b1;
            *reinterpret_cast<float2*>(gi + (size_t)(r0g + rr*8)*768 + c0) = v;
        }
    }
}

// ---------------- GRU scan (single intra-step syncthreads) --------------------
__device__ __forceinline__ void st_cluster_f32(unsigned laddr, int rank, float v){
    unsigned raddr;
    asm volatile("mapa.shared::cluster.u32 %0, %1, %2;" : "=r"(raddr) : "r"(laddr), "r"(rank));
    asm volatile("st.shared::cluster.f32 [%0], %1;" :: "r"(raddr), "f"(v) : "memory");
}
__device__ __forceinline__ void cluster_sync_all(){
    asm volatile("barrier.cluster.arrive.aligned;" ::: "memory");
    asm volatile("barrier.cluster.wait.aligned;"   ::: "memory");
}

#define GRU_SMEM_FLOATS 28192
#define GRU_SMEM_BYTES  (GRU_SMEM_FLOATS*4)

__global__ void __launch_bounds__(384) __cluster_dims__(8,1,1)
gru_kernel(const float* __restrict__ gi, const float* __restrict__ Wh,
           const float* __restrict__ bhn, __nv_bfloat16* __restrict__ cp_out)
{
    extern __shared__ float sm[];
    float* Whs   = sm;            // [256][96]
    float* h2    = sm + 24576;    // [2][256][4]
    float* part  = sm + 26624;    // [q*4+b][96]
    float* bhn_s = sm + 28160;    // [32]

    const int tid  = threadIdx.x;
    const int rank = blockIdx.x & 7;
    const int b0   = (blockIdx.x >> 3) * 4;
    const int u0   = rank * 32;

    for (int i = tid; i < 256*96; i += 384){
        int u = i / 96, c = i % 96;
        int gcol = (c >> 5)*256 + u0 + (c & 31);
        Whs[i] = Wh[u*768 + gcol];
    }
    for (int i = tid; i < 2048; i += 384) h2[i] = 0.f;
    if (tid < 32) bhn_s[tid] = bhn[u0 + tid];
    __syncthreads();
    cluster_sync_all();

    const int c  = tid % 96;
    const int q  = tid / 96;
    const int b3 = tid >> 5;
    const int ul = tid & 31;

    int cur = 0;
    for (int t = 0; t < NT; t++){
        float gir=0.f, giz=0.f, gin=0.f;
        if (tid < 128){
            const float* gp = gi + ((size_t)(b0+b3)*NT + t)*768;
            gir = gp[u0+ul]; giz = gp[256+u0+ul]; gin = gp[512+u0+ul];
        }
        {
            const float* hb = h2 + cur*1024;
            float a0=0.f,a1=0.f,a2=0.f,a3=0.f;
            const int ub = q*64;
#pragma unroll 8
            for (int uu = 0; uu < 64; uu++){
                int u = ub + uu;
                float w = Whs[u*96 + c];
                float4 h4 = *reinterpret_cast<const float4*>(hb + u*4);
                a0 += w*h4.x; a1 += w*h4.y; a2 += w*h4.z; a3 += w*h4.w;
            }
            part[(q*4+0)*96 + c] = a0;
            part[(q*4+1)*96 + c] = a1;
            part[(q*4+2)*96 + c] = a2;
            part[(q*4+3)*96 + c] = a3;
        }
        __syncthreads();

        int nxt = cur ^ 1;
        if (tid < 128){
            float hr = part[(0*4+b3)*96 + ul]      + part[(1*4+b3)*96 + ul]
                     + part[(2*4+b3)*96 + ul]      + part[(3*4+b3)*96 + ul];
            float hz = part[(0*4+b3)*96 + 32 + ul] + part[(1*4+b3)*96 + 32 + ul]
                     + part[(2*4+b3)*96 + 32 + ul] + part[(3*4+b3)*96 + 32 + ul];
            float hn = part[(0*4+b3)*96 + 64 + ul] + part[(1*4+b3)*96 + 64 + ul]
                     + part[(2*4+b3)*96 + 64 + ul] + part[(3*4+b3)*96 + 64 + ul];
            float r  = 1.f/(1.f + expf(-(gir + hr)));
            float zz = 1.f/(1.f + expf(-(giz + hz)));
            float n  = tanhf(gin + r*(hn + bhn_s[ul]));
            float hp = h2[cur*1024 + (u0+ul)*4 + b3];
            float hnew = (1.f - zz)*n + zz*hp;
            int g = u0 + ul;
            size_t base = (((size_t)(b0+b3)*NT + t))*512 + (size_t)(g>>7)*256 + (g & 127);
            __nv_bfloat16 hh = __float2bfloat16(hnew);
            cp_out[base]       = hh;
            cp_out[base + 128] = __float2bfloat16(hnew - __bfloat162float(hh));
            unsigned laddr = smem_u32(h2 + nxt*1024 + (u0+ul)*4 + b3);
#pragma unroll
            for (int r8 = 0; r8 < 8; r8++) st_cluster_f32(laddr, r8, hnew);
        }
        cluster_sync_all();
        cur = nxt;
    }
}

// ---------------- fused pred + streaming-softmax loss --------------------------
// smem: one 128-row buffer (67.6 KB). Phase 1 stages Wp there (A loaded direct
// from global as mma fragments). Phase 2 reuses it as two 64-row Z buffers.
// 2 CTAs/SM for latency hiding.
#define LOSS_RS 264
#define ZT_ROWS 64
#define LOSS_SMEM_BYTES (128*LOSS_RS*2)

__global__ void __launch_bounds__(256,2) loss_fused_kernel(
    const __nv_bfloat16* __restrict__ cp, const __nv_bfloat16* __restrict__ wps,
    const float* __restrict__ bp, const __nv_bfloat16* __restrict__ zp,
    float* __restrict__ out)
{
    extern __shared__ __align__(16) char lsm[];
    __nv_bfloat16* Sbuf = reinterpret_cast<__nv_bfloat16*>(lsm);
    const uint32_t Sb = smem_u32(Sbuf);
    const uint32_t SZb[2] = { Sb, Sb + ZT_ROWS*LOSS_RS*2 };
    __shared__ float wsum[16];

    const int tid  = threadIdx.x;
    const int warp = tid >> 5;
    const int lane = tid & 31;
    const int b    = blockIdx.y;
    const int k    = blockIdx.z + 1;
    const int t0   = blockIdx.x * 128;
    const int Tm   = NT - k;
    const int kk   = k - 1;
    const int mg   = b*NT + t0;

    const uint32_t lrow = (lane & 7) + ((lane >> 3) & 1)*8;
    const uint32_t lcol = (lane >> 4)*8;
    const int mw = warp * 16;

    // ================= Phase 1: pred A-tile (A from global, Wp in smem) =======
    float acc[16][4];
#pragma unroll
    for (int nf = 0; nf < 16; nf++)
#pragma unroll
        for (int i = 0; i < 4; i++) acc[nf][i] = 0.f;

    for (int khalf = 0; khalf < 2; khalf++){
        // stage Wp tile (128 n-rows x 256) into Sbuf
        for (int it = 0; it < 16; it++){
            int idx = tid + it*256;
            int r = idx >> 5, u = idx & 31;
            *reinterpret_cast<uint4*>(Sbuf + r*LOSS_RS + u*8) =
                *reinterpret_cast<const uint4*>(wps + ((size_t)khalf*1536 + kk*128 + r)*256 + u*8);
        }
        __syncthreads();

        // per-thread base for direct A-fragment loads from cp
        const char* cb = reinterpret_cast<const char*>(
            cp + (size_t)(mg + mw + (lane >> 2))*512 + khalf*256 + (lane & 3)*2);
        const size_t row8 = 8*512*2;   // 8 rows stride in bytes

#pragma unroll
        for (int kc = 0; kc < 8; kc++){
            uint32_t ahi[4], alo[4];
            // hi chunk kc: cols kc*16 .. ; lo chunk kc+8: cols (kc+8)*16 ..
            const char* ph = cb + (kc*16)*2;
            const char* pl = cb + ((kc+8)*16)*2;
            ahi[0] = *reinterpret_cast<const uint32_t*>(ph);
            ahi[1] = *reinterpret_cast<const uint32_t*>(ph + row8);
            ahi[2] = *reinterpret_cast<const uint32_t*>(ph + 16);
            ahi[3] = *reinterpret_cast<const uint32_t*>(ph + row8 + 16);
            alo[0] = *reinterpret_cast<const uint32_t*>(pl);
            alo[1] = *reinterpret_cast<const uint32_t*>(pl + row8);
            alo[2] = *reinterpret_cast<const uint32_t*>(pl + 16);
            alo[3] = *reinterpret_cast<const uint32_t*>(pl + row8 + 16);
#pragma unroll
            for (int nf2 = 0; nf2 < 8; nf2++){
                uint32_t r0,r1,r2,r3;
                // B hi chunk (Whi): col kc*16
                uint32_t addr = Sb + ((nf2*16 + lrow)*LOSS_RS + kc*16 + lcol)*2;
                ldmatrix_x4(r0, r1, r2, r3, addr);
                mma16816(acc[nf2*2+0], ahi, r0, r2);
                mma16816(acc[nf2*2+1], ahi, r1, r3);
                mma16816(acc[nf2*2+0], alo, r0, r2);
                mma16816(acc[nf2*2+1], alo, r1, r3);
                // B lo chunk (Wlo): col (kc+8)*16, pairs with A hi only
                addr = Sb + ((nf2*16 + lrow)*LOSS_RS + (kc+8)*16 + lcol)*2;
                ldmatrix_x4(r0, r1, r2, r3, addr);
                mma16816(acc[nf2*2+0], ahi, r0, r2);
                mma16816(acc[nf2*2+1], ahi, r1, r3);
            }
        }
        __syncthreads();
    }

    // ---- issue Z tile 0 prefetch (64 rows) ----
    for (int it = 0; it < 8; it++){
        int idx = tid + it*256;
        int j = idx >> 5, u = idx & 31;
        int jr = k + j;
        uint32_t ok = (jr < NT) ? 16u : 0u;
        int jc = jr < NT ? jr : NT-1;
        cp_async16(SZb[0] + (uint32_t)(j*LOSS_RS + u*8)*2,
                   zp + ((size_t)(b*NT) + jc)*256 + u*8, ok);
    }
    CP_COMMIT();

    // ---- build split-bf16 A-fragments in registers ----
    uint32_t afr[16][4];
    {
        const int ct2 = (lane & 3)*2;
#pragma unroll
        for (int nf = 0; nf < 16; nf++){
            float b0 = bp[kk*128 + nf*8 + ct2];
            float b1 = bp[kk*128 + nf*8 + ct2 + 1];
            acc[nf][0] = (acc[nf][0] + b0) * INV_TEMP;
            acc[nf][1] = (acc[nf][1] + b1) * INV_TEMP;
            acc[nf][2] = (acc[nf][2] + b0) * INV_TEMP;
            acc[nf][3] = (acc[nf][3] + b1) * INV_TEMP;
        }
#pragma unroll
        for (int kc = 0; kc < 8; kc++){
#pragma unroll
            for (int r2 = 0; r2 < 4; r2++){
                int nf = 2*kc + (r2 >> 1);
                int e0 = (r2 & 1)*2, e1 = e0 + 1;
                float v0 = acc[nf][e0], v1 = acc[nf][e1];
                __nv_bfloat16 h0 = __float2bfloat16(v0);
                __nv_bfloat16 h1 = __float2bfloat16(v1);
                afr[kc][r2]   = pack2bf(h0, h1);
                afr[kc+8][r2] = pack2bf(__float2bfloat16(v0 - __bfloat162float(h0)),
                                        __float2bfloat16(v1 - __bfloat162float(h1)));
            }
        }
    }

    // ================= Phase 2: streaming softmax (8 x 64-row tiles) ==========
    const int ra = t0 + mw + (lane >> 2);
    const bool rv0 = ra < Tm, rv1 = (ra + 8) < Tm;
    float mr[2] = {-1e30f, -1e30f};
    float sr[2] = {0.f, 0.f};
    float tot = 0.f;

    for (int jt = 0; jt < 8; jt++){
        const int j0 = jt * ZT_ROWS;
        CP_WAIT0();
        __syncthreads();
        if (jt < 7){
            const int jn = (jt+1) * ZT_ROWS;
            const uint32_t dst = SZb[(jt+1) & 1];
            for (int it = 0; it < 8; it++){
                int idx = tid + it*256;
                int j = idx >> 5, u = idx & 31;
                int jr = k + jn + j;
                uint32_t ok = (jr < NT) ? 16u : 0u;
                int jc = jr < NT ? jr : NT-1;
                cp_async16(dst + (uint32_t)(j*LOSS_RS + u*8)*2,
                           zp + ((size_t)(b*NT) + jc)*256 + u*8, ok);
            }
            CP_COMMIT();
        }
        const uint32_t Zb = SZb[jt & 1];

        float lac[8][4];
#pragma unroll
        for (int nf = 0; nf < 8; nf++)
#pragma unroll
            for (int i = 0; i < 4; i++) lac[nf][i] = 0.f;

#pragma unroll
        for (int kc = 0; kc < 16; kc++){
#pragma unroll
            for (int nf2 = 0; nf2 < 4; nf2++){
                uint32_t r0,r1,r2,r3;
                uint32_t addr = Zb + (uint32_t)((nf2*16 + lrow)*LOSS_RS + kc*16 + lcol)*2;
                ldmatrix_x4(r0, r1, r2, r3, addr);
                if (kc < 8){
                    mma16816(lac[nf2*2+0], afr[kc],   r0, r2);
                    mma16816(lac[nf2*2+1], afr[kc],   r1, r3);
                    mma16816(lac[nf2*2+0], afr[kc+8], r0, r2);
                    mma16816(lac[nf2*2+1], afr[kc+8], r1, r3);
                } else {
                    mma16816(lac[nf2*2+0], afr[kc-8], r0, r2);
                    mma16816(lac[nf2*2+1], afr[kc-8], r1, r3);
                }
            }
        }

        if (j0 + ZT_ROWS <= Tm){
            float tm[2] = {-1e30f, -1e30f};
#pragma unroll
            for (int nf = 0; nf < 8; nf++){
                tm[0] = fmaxf(tm[0], fmaxf(lac[nf][0], lac[nf][1]));
                tm[1] = fmaxf(tm[1], fmaxf(lac[nf][2], lac[nf][3]));
            }
#pragma unroll
            for (int o = 1; o <= 2; o <<= 1){
                tm[0] = fmaxf(tm[0], __shfl_xor_sync(0xFFFFFFFFu, tm[0], o));
                tm[1] = fmaxf(tm[1], __shfl_xor_sync(0xFFFFFFFFu, tm[1], o));
            }
#pragma unroll
            for (int rr = 0; rr < 2; rr++){
                float nm = fmaxf(mr[rr], tm[rr]);
                sr[rr] *= __expf(mr[rr] - nm);
                mr[rr] = nm;
            }
            float ls0 = 0.f, ls1 = 0.f, lt0 = 0.f, lt1 = 0.f;
#pragma unroll
            for (int nf = 0; nf < 8; nf++){
                ls0 += __expf(lac[nf][0] - mr[0]) + __expf(lac[nf][1] - mr[0]);
                ls1 += __expf(lac[nf][2] - mr[1]) + __expf(lac[nf][3] - mr[1]);
                lt0 += lac[nf][0] + lac[nf][1];
                lt1 += lac[nf][2] + lac[nf][3];
            }
            sr[0] += ls0; sr[1] += ls1;
            if (rv0) tot += lt0;
            if (rv1) tot += lt1;
        } else {
            const int cbase = j0 + (lane & 3)*2;
            float tm[2] = {-1e30f, -1e30f};
#pragma unroll
            for (int nf = 0; nf < 8; nf++){
                int c0 = cbase + nf*8;
                bool v0 = c0 < Tm, v1 = (c0+1) < Tm;
                if (v0){ tm[0] = fmaxf(tm[0], lac[nf][0]); tm[1] = fmaxf(tm[1], lac[nf][2]); }
                if (v1){ tm[0] = fmaxf(tm[0], lac[nf][1]); tm[1] = fmaxf(tm[1], lac[nf][3]); }
            }
#pragma unroll
            for (int o = 1; o <= 2; o <<= 1){
                tm[0] = fmaxf(tm[0], __shfl_xor_sync(0xFFFFFFFFu, tm[0], o));
                tm[1] = fmaxf(tm[1], __shfl_xor_sync(0xFFFFFFFFu, tm[1], o));
            }
            if (tm[0] > -1e29f){
#pragma unroll
                for (int rr = 0; rr < 2; rr++){
                    float nm = fmaxf(mr[rr], tm[rr]);
                    sr[rr] *= __expf(mr[rr] - nm);
                    mr[rr] = nm;
                }
                float ls0 = 0.f, ls1 = 0.f, lt0 = 0.f, lt1 = 0.f;
#pragma unroll
                for (int nf = 0; nf < 8; nf++){
                    int c0 = cbase + nf*8;
#pragma unroll
                    for (int h = 0; h < 2; h++){
                        if (c0 + h < Tm){
                            ls0 += __expf(lac[nf][h]   - mr[0]);
                            ls1 += __expf(lac[nf][2+h] - mr[1]);
                            lt0 += lac[nf][h]; lt1 += lac[nf][2+h];
                        }
                    }
                }
                sr[0] += ls0; sr[1] += ls1;
                if (rv0) tot += lt0;
                if (rv1) tot += lt1;
            }
        }
        __syncthreads();
    }

    // ---- finalize ----
#pragma unroll
    for (int o = 1; o <= 2; o <<= 1){
        sr[0] += __shfl_xor_sync(0xFFFFFFFFu, sr[0], o);
        sr[1] += __shfl_xor_sync(0xFFFFFFFFu, sr[1], o);
    }
    float lse = 0.f;
    if ((lane & 3) == 0){
        if (rv0) lse += mr[0] + __logf(sr[0]);
        if (rv1) lse += mr[1] + __logf(sr[1]);
    }
#pragma unroll
    for (int o = 16; o; o >>= 1){
        lse += __shfl_xor_sync(0xFFFFFFFFu, lse, o);
        tot += __shfl_xor_sync(0xFFFFFFFFu, tot, o);
    }
    if (lane == 0){ wsum[warp] = lse; wsum[8+warp] = tot; }
    __syncthreads();
    if (tid == 0){
        float L = 0.f, T = 0.f;
#pragma unroll
        for (int w = 0; w < 8; w++){ L += wsum[w]; T += wsum[8+w]; }
        float inv = 1.0f / ((float)NB * (float)Tm * (float)NK);
        atomicAdd(out, L*inv - T*(inv/(float)Tm));
    }
}

// ---------------- launch ------------------------------------------------------
extern "C" void kernel_launch(void* const* d_in, const int* in_sizes, int n_in,
                              void* d_out, int out_size)
{
    const float* x_seq  = (const float*)d_in[0];
    const float* W_enc  = (const float*)d_in[1];
    const float* b_enc  = (const float*)d_in[2];
    const float* W_proj = (const float*)d_in[3];
    const float* b_proj = (const float*)d_in[4];
    const float* Wi     = (const float*)d_in[5];
    const float* bi     = (const float*)d_in[6];
    const float* Wh     = (const float*)d_in[7];
    const float* bhn    = (const float*)d_in[8];
    const float* Wp     = (const float*)d_in[9];
    const float* bp     = (const float*)d_in[10];
    float* out = (float*)d_out;

    float *Wf, *bz, *gibuf;
    __nv_bfloat16 *zpb, *cpb, *wpsb, *wisb;
    cudaGetSymbolAddress((void**)&Wf,    g_Wf);
    cudaGetSymbolAddress((void**)&bz,    g_bz);
    cudaGetSymbolAddress((void**)&gibuf, g_gi);
    cudaGetSymbolAddress((void**)&zpb,   g_zp);
    cudaGetSymbolAddress((void**)&cpb,   g_cp);
    cudaGetSymbolAddress((void**)&wpsb,  g_wps);
    cudaGetSymbolAddress((void**)&wisb,  g_wis);

    cudaFuncSetAttribute(gru_kernel,        cudaFuncAttributeMaxDynamicSharedMemorySize, GRU_SMEM_BYTES);
    cudaFuncSetAttribute(loss_fused_kernel, cudaFuncAttributeMaxDynamicSharedMemorySize, LOSS_SMEM_BYTES);
    cudaFuncSetAttribute(gi_mma_kernel,     cudaFuncAttributeMaxDynamicSharedMemorySize, GI_SMEM_BYTES);

    zero_loss_kernel<<<1, 32>>>(out);
    bz_kernel<<<1, 128>>>(b_enc, W_proj, b_proj, bz);

    // Wf = W_enc @ W_proj   (256x128x256)
    gemm_bias_kernel<<<dim3(1,2), 256>>>(W_enc, W_proj, nullptr, Wf, 256, 128, 256);
    // zp = split(x @ Wf + bz)
    zgemm_pack_kernel<<<dim3(1,256), 256>>>(x_seq, Wf, bz, zpb);
    // Wi split pack
    repack_wi_kernel<<<(128*768+255)/256, 256>>>(Wi, wisb);
    // gi = z @ Wi + bi  (tensor path)
    gi_mma_kernel<<<dim3(6,256), 256, GI_SMEM_BYTES>>>(zpb, wisb, bi, gibuf);
    // Wp split pack
    repack_wp_kernel<<<768, 512>>>(Wp, wpsb);
    // GRU scan (persistent, clustered; writes split c directly)
    gru_kernel<<<128, 384, GRU_SMEM_BYTES>>>(gibuf, Wh, bhn, cpb);
    // fused pred + streaming-softmax loss (67.6 KB smem, 2 CTAs/SM)
    loss_fused_kernel<<<dim3(4,64,12), 256, LOSS_SMEM_BYTES>>>(cpb, wpsb, bp, zpb, out);
}